// round 7
// baseline (speedup 1.0000x reference)
#include <cuda_runtime.h>
#include <cstdint>

// Problem constants
#define B_    4
#define L_    1024
#define V_    1280
#define E_    768
#define NBIN  8
#define NHID  32

// Output layout: concat(logits[B,L,8,V], tte[B,L,V], mask[B,L,8,V]) fp32
#define TTE_OFF    ((size_t)B_ * L_ * NBIN * V_)                 // 41943040
#define MASK_OFF   (TTE_OFF + (size_t)B_ * L_ * V_)              // 47185920

// Scratch: x = h @ W1, stored TRANSPOSED per row: g_x[row*256 + h*8 + n]
__device__ float g_x[(size_t)B_ * L_ * NBIN * NHID];
// Seed table: g_seed[b][chunk][v] = next occurrence index >= (chunk+1)*32
__device__ int g_seed[(size_t)B_ * 32 * V_];

typedef unsigned long long u64;
union F4U2 { float4 f; u64 u[2]; };

__device__ __forceinline__ u64 pk(float lo, float hi) {
    u64 r; asm("mov.b64 %0, {%1,%2};" : "=l"(r) : "f"(lo), "f"(hi)); return r;
}
__device__ __forceinline__ void upk(u64 v, float& lo, float& hi) {
    asm("mov.b64 {%0,%1}, %2;" : "=f"(lo), "=f"(hi) : "l"(v));
}
__device__ __forceinline__ void fma2(u64& d, u64 a, u64 b) {
    asm("fma.rn.f32x2 %0, %1, %2, %0;" : "+l"(d) : "l"(a), "l"(b));
}

// ---------------------------------------------------------------------------
// Kernel 1: x = h @ W1   (M=4096, K=768, N=256).  128x64 tile, 256 threads,
// 8x4 per thread, diagonal-packed FFMA2.  Writes g_x in [h][bin] layout.
// ---------------------------------------------------------------------------
__global__ __launch_bounds__(256) void k_gemm1(const float* __restrict__ A,
                                               const float* __restrict__ W1) {
    __shared__ float As[16][132];   // [k][row]
    __shared__ float Bs[16][68];    // [k][col]
    const int K = E_, N = NBIN * NHID;
    int bx = blockIdx.x;                 // 0..3   (N/64)
    int by = blockIdx.y;                 // 0..31  (M/128)
    int tid = threadIdx.x;
    int tx = tid & 15, ty = tid >> 4;
    int rowBase = by * 128, colBase = bx * 64;

    u64 c[4][4];
#pragma unroll
    for (int i = 0; i < 4; i++)
#pragma unroll
        for (int j = 0; j < 4; j++) c[i][j] = 0;

    for (int k0 = 0; k0 < K; k0 += 16) {
#pragma unroll
        for (int p = 0; p < 8; p++) {          // 128x16 A tile
            int idx = tid + p * 256;
            int r = idx >> 4, cc = idx & 15;
            As[cc][r] = A[(size_t)(rowBase + r) * K + k0 + cc];
        }
#pragma unroll
        for (int p = 0; p < 4; p++) {          // 16x64 B tile
            int idx = tid + p * 256;
            int r = idx >> 6, cc = idx & 63;
            Bs[r][cc] = W1[(size_t)(k0 + r) * N + colBase + cc];
        }
        __syncthreads();
#pragma unroll
        for (int kk = 0; kk < 16; kk++) {
            F4U2 alo, ahi, bv;
            alo.f = *(const float4*)&As[kk][ty * 8];
            ahi.f = *(const float4*)&As[kk][ty * 8 + 4];
            bv.f  = *(const float4*)&Bs[kk][tx * 4];
            u64 ap0 = alo.u[0], ap1 = alo.u[1], ap2 = ahi.u[0], ap3 = ahi.u[1];
            u64 b01 = bv.u[0], b23 = bv.u[1];
            u64 b12 = pk(bv.f.y, bv.f.z);
            u64 b30 = pk(bv.f.w, bv.f.x);
            fma2(c[0][0], ap0, b01); fma2(c[0][1], ap0, b12);
            fma2(c[0][2], ap0, b23); fma2(c[0][3], ap0, b30);
            fma2(c[1][0], ap1, b01); fma2(c[1][1], ap1, b12);
            fma2(c[1][2], ap1, b23); fma2(c[1][3], ap1, b30);
            fma2(c[2][0], ap2, b01); fma2(c[2][1], ap2, b12);
            fma2(c[2][2], ap2, b23); fma2(c[2][3], ap2, b30);
            fma2(c[3][0], ap3, b01); fma2(c[3][1], ap3, b12);
            fma2(c[3][2], ap3, b23); fma2(c[3][3], ap3, b30);
        }
        __syncthreads();
    }

    float o[8][4];
#pragma unroll
    for (int rp = 0; rp < 4; rp++) {
        upk(c[rp][0], o[2*rp][0], o[2*rp+1][1]);
        upk(c[rp][1], o[2*rp][1], o[2*rp+1][2]);
        upk(c[rp][2], o[2*rp][2], o[2*rp+1][3]);
        upk(c[rp][3], o[2*rp][3], o[2*rp+1][0]);
    }
#pragma unroll
    for (int rr = 0; rr < 8; rr++) {
        size_t rbase = (size_t)(rowBase + ty * 8 + rr) * 256;
#pragma unroll
        for (int j = 0; j < 4; j++) {
            int col = colBase + tx * 4 + j;       // original col = n*32+h
            int pc = (col & 31) * 8 + (col >> 5); // transposed [h][n]
            g_x[rbase + pc] = o[rr][j];
        }
    }
}

// ---------------------------------------------------------------------------
// Kernel 2a: seed scan.  grid (vb=5, b=4), 256 threads, 1 v per thread.
// ---------------------------------------------------------------------------
__global__ __launch_bounds__(256) void k_seed(const int* __restrict__ targets) {
    __shared__ int tg[L_];
    int b = blockIdx.y;
    int v = blockIdx.x * 256 + threadIdx.x;
    for (int i = threadIdx.x; i < L_; i += 256)
        tg[i] = targets[(size_t)b * L_ + i];
    __syncthreads();

    int* seed = g_seed + (size_t)b * 32 * V_;
    int nxt = L_;
#pragma unroll 1
    for (int ch = 31; ch >= 0; --ch) {
        seed[(size_t)ch * V_ + v] = nxt;
#pragma unroll
        for (int ii = 31; ii >= 0; --ii) {
            int i = ch * 32 + ii;
            if (tg[i] == v) nxt = i;
        }
    }
}

// ---------------------------------------------------------------------------
// Fat kernel: heterogeneous blocks.
//   blockIdx.x <  256 : tte+mask writer (store/DRAM-bound; STG.128 only)
//   blockIdx.x >= 256 : gemm2 tile (fma-bound; 256m x 64v, 16m x 4v/thread)
// tte blocks first so wave 1 co-schedules both kinds on every SM.
// ---------------------------------------------------------------------------
struct GemmSmem { float As[32][264]; float Bs[32][68]; };
struct TteSmem  { float ta[L_]; float ag[32]; int tg[32]; };

__global__ __launch_bounds__(256) void k_fat(const float* __restrict__ W2,
                                             const float* __restrict__ age,
                                             const float* __restrict__ targets_age,
                                             const int* __restrict__ targets,
                                             float* __restrict__ out) {
    __shared__ __align__(16) char smem_raw[sizeof(GemmSmem)];
    int tid = threadIdx.x;

    if (blockIdx.x < 256) {
        // ---------------- tte + mask path (from R4's k_tte_write) ----------
        TteSmem& S = *(TteSmem*)smem_raw;
        int t     = blockIdx.x;
        int half  = t & 1;              // which 640-v half
        int bc    = t >> 1;             // 0..127
        int b     = bc >> 5;
        int chunk = bc & 31;
        int i0    = chunk * 32;

        ((float4*)S.ta)[tid] = ((const float4*)(targets_age + (size_t)b * L_))[tid];
        if (tid < 32) {
            S.ag[tid] = age[(size_t)b * L_ + i0 + tid];
            S.tg[tid] = targets[(size_t)b * L_ + i0 + tid];
        }
        __syncthreads();

        if (tid < 160) {
            int v0 = half * 640 + 4 * tid;
            int4 sd = *(const int4*)&g_seed[((size_t)b * 32 + chunk) * V_ + v0];
            int nxt[4] = {sd.x, sd.y, sd.z, sd.w};

            float* out_tte  = out + TTE_OFF  + (size_t)b * L_ * V_;
            float* out_mask = out + MASK_OFF + (size_t)b * L_ * NBIN * V_;
            bool isv0 = (v0 == 0);

            for (int ii = 31; ii >= 0; --ii) {
                int i = i0 + ii;
                int tg = S.tg[ii];
#pragma unroll
                for (int k = 0; k < 4; k++)
                    if (tg == v0 + k) nxt[k] = i;

                float a = S.ag[ii];
                float tt[4]; bool ne[4];
#pragma unroll
                for (int k = 0; k < 4; k++) {
                    int idx = nxt[k];
                    if (isv0 && k == 0 && i >= 1) idx = 0;
                    ne[k] = (idx == L_);
                    tt[k] = S.ta[ne[k] ? (L_ - 1) : idx] - a;
                }
                *(float4*)&out_tte[(size_t)i * V_ + v0] =
                    make_float4(tt[0], tt[1], tt[2], tt[3]);

                size_t mbase = (size_t)i * NBIN * V_ + v0;
#pragma unroll
                for (int n = 0; n < NBIN; n++) {
                    float lo = 1.25f * n;
                    float hi = lo + 1.25f;
                    float4 m;
                    m.x = ((tt[0] >= lo && tt[0] < hi) || ne[0]) ? 1.0f : 0.0f;
                    m.y = ((tt[1] >= lo && tt[1] < hi) || ne[1]) ? 1.0f : 0.0f;
                    m.z = ((tt[2] >= lo && tt[2] < hi) || ne[2]) ? 1.0f : 0.0f;
                    m.w = ((tt[3] >= lo && tt[3] < hi) || ne[3]) ? 1.0f : 0.0f;
                    *(float4*)&out_mask[mbase + (size_t)n * V_] = m;
                }
            }
        }
        return;
    }

    // ---------------- gemm2 tile path (16m x 4v micro-tile) ----------------
    GemmSmem& S = *(GemmSmem*)smem_raw;
    int t  = blockIdx.x - 256;       // 0..2559
    int bx = t % 20, by = t / 20;
    int tx = tid & 15, ty = tid >> 4;
    int v0 = bx * 64;
    int m0 = by * 256;
    int row0 = m0 >> 3;

    // A tile: 32 g_x rows (= 256 m) x 256 floats, contiguous 32KB.
    const float4* xsrc = (const float4*)(g_x + (size_t)row0 * 256);
#pragma unroll
    for (int p = 0; p < 8; p++) {
        int idx = tid + p * 256;            // 2048 float4
        float4 v4 = xsrc[idx];
        int rl = idx >> 6;                  // 0..31
        int rem = idx & 63;
        int h = rem >> 1, n4 = (rem & 1) << 2;
        *(float4*)&S.As[h][rl * 8 + n4] = v4;
    }
    // B tile: W2[h][v0+vl], 32x64
#pragma unroll
    for (int p = 0; p < 2; p++) {
        int idx = tid + p * 256;            // 512 float4
        int h = idx >> 4, vq = (idx & 15) << 2;
        *(float4*)&S.Bs[h][vq] = *(const float4*)&W2[(size_t)h * V_ + v0 + vq];
    }
    __syncthreads();

    u64 acc[8][4];
#pragma unroll
    for (int i = 0; i < 8; i++)
#pragma unroll
        for (int j = 0; j < 4; j++) acc[i][j] = 0;

#pragma unroll 8
    for (int k = 0; k < 32; k++) {
        F4U2 a0, a1, a2, a3, bv;
        a0.f = *(const float4*)&S.As[k][ty * 16];
        a1.f = *(const float4*)&S.As[k][ty * 16 + 4];
        a2.f = *(const float4*)&S.As[k][ty * 16 + 8];
        a3.f = *(const float4*)&S.As[k][ty * 16 + 12];
        bv.f = *(const float4*)&S.Bs[k][tx * 4];
        u64 ap[8] = {a0.u[0], a0.u[1], a1.u[0], a1.u[1],
                     a2.u[0], a2.u[1], a3.u[0], a3.u[1]};
        u64 bp0 = bv.u[0], bp2 = bv.u[1];
        u64 bp1 = pk(bv.f.y, bv.f.z);
        u64 bp3 = pk(bv.f.w, bv.f.x);
#pragma unroll
        for (int i = 0; i < 8; i++) {
            fma2(acc[i][0], ap[i], bp0);
            fma2(acc[i][1], ap[i], bp1);
            fma2(acc[i][2], ap[i], bp2);
            fma2(acc[i][3], ap[i], bp3);
        }
    }

    // Decode diagonal pairs and store two rows at a time (limits live floats)
#pragma unroll
    for (int i = 0; i < 8; i++) {
        float c0[4], c1[4];
        upk(acc[i][0], c0[0], c1[1]);
        upk(acc[i][1], c0[1], c1[2]);
        upk(acc[i][2], c0[2], c1[3]);
        upk(acc[i][3], c0[3], c1[0]);
        size_t off0 = (size_t)(m0 + ty * 16 + 2 * i) * V_ + v0 + tx * 4;
        *(float4*)&out[off0]      = make_float4(c0[0], c0[1], c0[2], c0[3]);
        *(float4*)&out[off0 + V_] = make_float4(c1[0], c1[1], c1[2], c1[3]);
    }
}

// ---------------------------------------------------------------------------
static cudaStream_t g_s2;
static cudaEvent_t g_e1, g_e2;
static struct StreamInit {
    StreamInit() {
        cudaStreamCreateWithFlags(&g_s2, cudaStreamNonBlocking);
        cudaEventCreateWithFlags(&g_e1, cudaEventDisableTiming);
        cudaEventCreateWithFlags(&g_e2, cudaEventDisableTiming);
    }
} g_stream_init;

extern "C" void kernel_launch(void* const* d_in, const int* in_sizes, int n_in,
                              void* d_out, int out_size) {
    const float* h       = (const float*)d_in[0];  // (B,L,768)
    const float* age     = (const float*)d_in[1];  // (B,L)
    const float* tage    = (const float*)d_in[2];  // (B,L)
    const int*   targets = (const int*)d_in[4];    // (B,L) int32
    const float* W1      = (const float*)d_in[5];  // (768,256)
    const float* W2      = (const float*)d_in[6];  // (32,1280)
    float* out = (float*)d_out;

    // Seeds (stream 2) overlap gemm1 (stream 0); fat kernel joins both.
    cudaEventRecord(g_e1, 0);
    cudaStreamWaitEvent(g_s2, g_e1, 0);
    k_seed<<<dim3(5, B_), 256, 0, g_s2>>>(targets);
    cudaEventRecord(g_e2, g_s2);

    k_gemm1<<<dim3(4, 32), 256>>>(h, W1);
    cudaStreamWaitEvent(0, g_e2, 0);
    k_fat<<<256 + 2560, 256>>>(W2, age, tage, targets, out);
}

// round 8
// speedup vs baseline: 1.0813x; 1.0813x over previous
#include <cuda_runtime.h>
#include <cstdint>

// Problem constants
#define B_    4
#define L_    1024
#define V_    1280
#define E_    768
#define NBIN  8
#define NHID  32

// Output layout: concat(logits[B,L,8,V], tte[B,L,V], mask[B,L,8,V]) fp32
#define TTE_OFF    ((size_t)B_ * L_ * NBIN * V_)                 // 41943040
#define MASK_OFF   (TTE_OFF + (size_t)B_ * L_ * V_)              // 47185920

// Scratch: x = h @ W1, stored TRANSPOSED per row: g_x[row*256 + h*8 + n]
__device__ float g_x[(size_t)B_ * L_ * NBIN * NHID];
// Seed table (16-row granularity): g_seed[b][chunk][v] = next occurrence
// index of v at position >= (chunk+1)*16 ; chunk in [0,64)
__device__ int g_seed[(size_t)B_ * 64 * V_];

typedef unsigned long long u64;
union F4U2 { float4 f; u64 u[2]; };

__device__ __forceinline__ u64 pk(float lo, float hi) {
    u64 r; asm("mov.b64 %0, {%1,%2};" : "=l"(r) : "f"(lo), "f"(hi)); return r;
}
__device__ __forceinline__ void upk(u64 v, float& lo, float& hi) {
    asm("mov.b64 {%0,%1}, %2;" : "=f"(lo), "=f"(hi) : "l"(v));
}
__device__ __forceinline__ void fma2(u64& d, u64 a, u64 b) {
    asm("fma.rn.f32x2 %0, %1, %2, %0;" : "+l"(d) : "l"(a), "l"(b));
}

// ---------------------------------------------------------------------------
// Kernel 1: x = h @ W1   (M=4096, K=768, N=256).  128x64 tile, 256 threads,
// 8x4 per thread, diagonal-packed FFMA2.  Writes g_x in [h][bin] layout.
// ---------------------------------------------------------------------------
__global__ __launch_bounds__(256) void k_gemm1(const float* __restrict__ A,
                                               const float* __restrict__ W1) {
    __shared__ float As[16][132];   // [k][row]
    __shared__ float Bs[16][68];    // [k][col]
    const int K = E_, N = NBIN * NHID;
    int bx = blockIdx.x;                 // 0..3   (N/64)
    int by = blockIdx.y;                 // 0..31  (M/128)
    int tid = threadIdx.x;
    int tx = tid & 15, ty = tid >> 4;
    int rowBase = by * 128, colBase = bx * 64;

    u64 c[4][4];
#pragma unroll
    for (int i = 0; i < 4; i++)
#pragma unroll
        for (int j = 0; j < 4; j++) c[i][j] = 0;

    for (int k0 = 0; k0 < K; k0 += 16) {
#pragma unroll
        for (int p = 0; p < 8; p++) {          // 128x16 A tile
            int idx = tid + p * 256;
            int r = idx >> 4, cc = idx & 15;
            As[cc][r] = A[(size_t)(rowBase + r) * K + k0 + cc];
        }
#pragma unroll
        for (int p = 0; p < 4; p++) {          // 16x64 B tile
            int idx = tid + p * 256;
            int r = idx >> 6, cc = idx & 63;
            Bs[r][cc] = W1[(size_t)(k0 + r) * N + colBase + cc];
        }
        __syncthreads();
#pragma unroll
        for (int kk = 0; kk < 16; kk++) {
            F4U2 alo, ahi, bv;
            alo.f = *(const float4*)&As[kk][ty * 8];
            ahi.f = *(const float4*)&As[kk][ty * 8 + 4];
            bv.f  = *(const float4*)&Bs[kk][tx * 4];
            u64 ap0 = alo.u[0], ap1 = alo.u[1], ap2 = ahi.u[0], ap3 = ahi.u[1];
            u64 b01 = bv.u[0], b23 = bv.u[1];
            u64 b12 = pk(bv.f.y, bv.f.z);
            u64 b30 = pk(bv.f.w, bv.f.x);
            fma2(c[0][0], ap0, b01); fma2(c[0][1], ap0, b12);
            fma2(c[0][2], ap0, b23); fma2(c[0][3], ap0, b30);
            fma2(c[1][0], ap1, b01); fma2(c[1][1], ap1, b12);
            fma2(c[1][2], ap1, b23); fma2(c[1][3], ap1, b30);
            fma2(c[2][0], ap2, b01); fma2(c[2][1], ap2, b12);
            fma2(c[2][2], ap2, b23); fma2(c[2][3], ap2, b30);
            fma2(c[3][0], ap3, b01); fma2(c[3][1], ap3, b12);
            fma2(c[3][2], ap3, b23); fma2(c[3][3], ap3, b30);
        }
        __syncthreads();
    }

    float o[8][4];
#pragma unroll
    for (int rp = 0; rp < 4; rp++) {
        upk(c[rp][0], o[2*rp][0], o[2*rp+1][1]);
        upk(c[rp][1], o[2*rp][1], o[2*rp+1][2]);
        upk(c[rp][2], o[2*rp][2], o[2*rp+1][3]);
        upk(c[rp][3], o[2*rp][3], o[2*rp+1][0]);
    }
#pragma unroll
    for (int rr = 0; rr < 8; rr++) {
        size_t rbase = (size_t)(rowBase + ty * 8 + rr) * 256;
#pragma unroll
        for (int j = 0; j < 4; j++) {
            int col = colBase + tx * 4 + j;       // original col = n*32+h
            int pc = (col & 31) * 8 + (col >> 5); // transposed [h][n]
            g_x[rbase + pc] = o[rr][j];
        }
    }
}

// ---------------------------------------------------------------------------
// Kernel 2a: seed scan, 16-row granularity.  grid (vb=5, b=4), 256 threads.
// ---------------------------------------------------------------------------
__global__ __launch_bounds__(256) void k_seed(const int* __restrict__ targets) {
    __shared__ int tg[L_];
    int b = blockIdx.y;
    int v = blockIdx.x * 256 + threadIdx.x;
    for (int i = threadIdx.x; i < L_; i += 256)
        tg[i] = targets[(size_t)b * L_ + i];
    __syncthreads();

    int* seed = g_seed + (size_t)b * 64 * V_;
    int nxt = L_;
#pragma unroll 1
    for (int ch = 63; ch >= 0; --ch) {
        seed[(size_t)ch * V_ + v] = nxt;   // occurrences at index >= (ch+1)*16
#pragma unroll
        for (int ii = 15; ii >= 0; --ii) {
            int i = ch * 16 + ii;
            if (tg[i] == v) nxt = i;
        }
    }
}

// ---------------------------------------------------------------------------
// Kernel 2b: tte + mask writer.  grid (chunk=64, b=4) = 256 blocks,
// 320 threads, 4 consecutive v per thread, 16 rows per block; STG.128 only.
// Special case (scatter semantics): token_index[b, i>=1, v=0] = 0.
// ---------------------------------------------------------------------------
__global__ __launch_bounds__(320) void k_tte_write(const int* __restrict__ targets,
                                                   const float* __restrict__ age,
                                                   const float* __restrict__ targets_age,
                                                   float* __restrict__ out) {
    __shared__ float ta[L_];
    __shared__ float ag_s[16];
    __shared__ int   tg_s[16];

    int b     = blockIdx.y;
    int chunk = blockIdx.x;          // 0..63
    int i0    = chunk * 16;
    int tid   = threadIdx.x;
    int v0    = 4 * tid;             // 0..1276

    if (tid < 256)
        ((float4*)ta)[tid] = ((const float4*)(targets_age + (size_t)b * L_))[tid];
    if (tid < 16) {
        ag_s[tid] = age[(size_t)b * L_ + i0 + tid];
        tg_s[tid] = targets[(size_t)b * L_ + i0 + tid];
    }
    __syncthreads();

    int4 sd = *(const int4*)&g_seed[((size_t)b * 64 + chunk) * V_ + v0];
    int nxt[4] = {sd.x, sd.y, sd.z, sd.w};

    float* out_tte  = out + TTE_OFF  + (size_t)b * L_ * V_;
    float* out_mask = out + MASK_OFF + (size_t)b * L_ * NBIN * V_;
    bool isv0 = (v0 == 0);

#pragma unroll 1
    for (int ii = 15; ii >= 0; --ii) {
        int i = i0 + ii;
        int t = tg_s[ii];
#pragma unroll
        for (int k = 0; k < 4; k++)
            if (t == v0 + k) nxt[k] = i;

        float a = ag_s[ii];
        float tt[4]; bool ne[4];
#pragma unroll
        for (int k = 0; k < 4; k++) {
            int idx = nxt[k];
            if (isv0 && k == 0 && i >= 1) idx = 0;
            ne[k] = (idx == L_);
            tt[k] = ta[ne[k] ? (L_ - 1) : idx] - a;
        }
        *(float4*)&out_tte[(size_t)i * V_ + v0] = make_float4(tt[0], tt[1], tt[2], tt[3]);

        size_t mbase = (size_t)i * NBIN * V_ + v0;
#pragma unroll
        for (int n = 0; n < NBIN; n++) {
            float lo = 1.25f * n;
            float hi = lo + 1.25f;
            float4 m;
            m.x = ((tt[0] >= lo && tt[0] < hi) || ne[0]) ? 1.0f : 0.0f;
            m.y = ((tt[1] >= lo && tt[1] < hi) || ne[1]) ? 1.0f : 0.0f;
            m.z = ((tt[2] >= lo && tt[2] < hi) || ne[2]) ? 1.0f : 0.0f;
            m.w = ((tt[3] >= lo && tt[3] < hi) || ne[3]) ? 1.0f : 0.0f;
            *(float4*)&out_mask[mbase + (size_t)n * V_] = m;
        }
    }
}

// ---------------------------------------------------------------------------
// Kernel 3: logits GEMM (M=32768, N=1280, K=32).  Tile 256m x 64v,
// 256 threads, 16m x 4v micro-tile.  A is warp-broadcast (2 addrs/warp),
// LDS ~384 B/warp/k, only 2 pk per k.  Diagonal-packed FFMA2.
// ---------------------------------------------------------------------------
__global__ __launch_bounds__(256) void k_gemm2(const float* __restrict__ W2,
                                               float* __restrict__ out) {
    __shared__ float As[32][264];   // [h][m_local] (pad de-conflicts stores)
    __shared__ float Bs[32][68];    // [h][v_local]
    int tid = threadIdx.x;
    int tx = tid & 15, ty = tid >> 4;
    int v0 = blockIdx.x * 64;       // 0..19
    int m0 = blockIdx.y * 256;      // 0..127
    int row0 = m0 >> 3;

    // A tile: 32 g_x rows (= 256 m) x 256 floats, contiguous 32KB.
    // g_x[r][h*8+n] -> As[h][rl*8+n]
    const float4* xsrc = (const float4*)(g_x + (size_t)row0 * 256);
#pragma unroll
    for (int p = 0; p < 8; p++) {
        int idx = tid + p * 256;            // 2048 float4
        float4 v4 = xsrc[idx];
        int rl = idx >> 6;                  // 0..31
        int rem = idx & 63;
        int h = rem >> 1, n4 = (rem & 1) << 2;
        *(float4*)&As[h][rl * 8 + n4] = v4;
    }
    // B tile: W2[h][v0+vl], 32x64
#pragma unroll
    for (int p = 0; p < 2; p++) {
        int idx = tid + p * 256;            // 512 float4
        int h = idx >> 4, vq = (idx & 15) << 2;
        *(float4*)&Bs[h][vq] = *(const float4*)&W2[(size_t)h * V_ + v0 + vq];
    }
    __syncthreads();

    u64 acc[8][4];
#pragma unroll
    for (int i = 0; i < 8; i++)
#pragma unroll
        for (int j = 0; j < 4; j++) acc[i][j] = 0;

#pragma unroll 8
    for (int k = 0; k < 32; k++) {
        F4U2 a0, a1, a2, a3, bv;
        a0.f = *(const float4*)&As[k][ty * 16];
        a1.f = *(const float4*)&As[k][ty * 16 + 4];
        a2.f = *(const float4*)&As[k][ty * 16 + 8];
        a3.f = *(const float4*)&As[k][ty * 16 + 12];
        bv.f = *(const float4*)&Bs[k][tx * 4];
        u64 ap[8] = {a0.u[0], a0.u[1], a1.u[0], a1.u[1],
                     a2.u[0], a2.u[1], a3.u[0], a3.u[1]};
        u64 bp0 = bv.u[0], bp2 = bv.u[1];
        u64 bp1 = pk(bv.f.y, bv.f.z);
        u64 bp3 = pk(bv.f.w, bv.f.x);
#pragma unroll
        for (int i = 0; i < 8; i++) {
            fma2(acc[i][0], ap[i], bp0);
            fma2(acc[i][1], ap[i], bp1);
            fma2(acc[i][2], ap[i], bp2);
            fma2(acc[i][3], ap[i], bp3);
        }
    }

    // Decode diagonal pairs, store two m-rows per acc group
#pragma unroll
    for (int i = 0; i < 8; i++) {
        float c0[4], c1[4];
        upk(acc[i][0], c0[0], c1[1]);
        upk(acc[i][1], c0[1], c1[2]);
        upk(acc[i][2], c0[2], c1[3]);
        upk(acc[i][3], c0[3], c1[0]);
        size_t off0 = (size_t)(m0 + ty * 16 + 2 * i) * V_ + v0 + tx * 4;
        *(float4*)&out[off0]      = make_float4(c0[0], c0[1], c0[2], c0[3]);
        *(float4*)&out[off0 + V_] = make_float4(c1[0], c1[1], c1[2], c1[3]);
    }
}

// ---------------------------------------------------------------------------
static cudaStream_t g_s2;
static cudaEvent_t g_e1, g_e2;
static struct StreamInit {
    StreamInit() {
        cudaStreamCreateWithFlags(&g_s2, cudaStreamNonBlocking);
        cudaEventCreateWithFlags(&g_e1, cudaEventDisableTiming);
        cudaEventCreateWithFlags(&g_e2, cudaEventDisableTiming);
    }
} g_stream_init;

extern "C" void kernel_launch(void* const* d_in, const int* in_sizes, int n_in,
                              void* d_out, int out_size) {
    const float* h       = (const float*)d_in[0];  // (B,L,768)
    const float* age     = (const float*)d_in[1];  // (B,L)
    const float* tage    = (const float*)d_in[2];  // (B,L)
    const int*   targets = (const int*)d_in[4];    // (B,L) int32
    const float* W1      = (const float*)d_in[5];  // (768,256)
    const float* W2      = (const float*)d_in[6];  // (32,1280)
    float* out = (float*)d_out;

    // Fork: seed -> tte_write on stream 2; gemm1 -> gemm2 on stream 0.
    cudaEventRecord(g_e1, 0);
    cudaStreamWaitEvent(g_s2, g_e1, 0);
    k_seed<<<dim3(5, B_), 256, 0, g_s2>>>(targets);
    k_tte_write<<<dim3(64, B_), 320, 0, g_s2>>>(targets, age, tage, out);
    cudaEventRecord(g_e2, g_s2);

    k_gemm1<<<dim3(4, 32), 256>>>(h, W1);
    k_gemm2<<<dim3(20, 128), 256>>>(W2, out);
    cudaStreamWaitEvent(0, g_e2, 0);
}

// round 10
// speedup vs baseline: 1.1371x; 1.0517x over previous
#include <cuda_runtime.h>
#include <cstdint>

// Problem constants
#define B_    4
#define L_    1024
#define V_    1280
#define E_    768
#define NBIN  8
#define NHID  32

// Output layout: concat(logits[B,L,8,V], tte[B,L,V], mask[B,L,8,V]) fp32
#define TTE_OFF    ((size_t)B_ * L_ * NBIN * V_)                 // 41943040
#define MASK_OFF   (TTE_OFF + (size_t)B_ * L_ * V_)              // 47185920

// Scratch: x = h @ W1, stored m-major as tf32 bit patterns:
// g_x[m*32 + h], m = (b*L+l)*8 + n   (tf32-rounded in gemm1's epilogue)
__device__ uint32_t g_x[(size_t)B_ * L_ * NBIN * NHID];
// Seed table (16-row granularity): g_seed[b][chunk][v] = next occurrence
// index of v at position >= (chunk+1)*16 ; chunk in [0,64)
__device__ int g_seed[(size_t)B_ * 64 * V_];

typedef unsigned long long u64;
union F4U2 { float4 f; u64 u[2]; };

__device__ __forceinline__ u64 pk(float lo, float hi) {
    u64 r; asm("mov.b64 %0, {%1,%2};" : "=l"(r) : "f"(lo), "f"(hi)); return r;
}
__device__ __forceinline__ void upk(u64 v, float& lo, float& hi) {
    asm("mov.b64 {%0,%1}, %2;" : "=f"(lo), "=f"(hi) : "l"(v));
}
__device__ __forceinline__ void fma2(u64& d, u64 a, u64 b) {
    asm("fma.rn.f32x2 %0, %1, %2, %0;" : "+l"(d) : "l"(a), "l"(b));
}
__device__ __forceinline__ uint32_t to_tf32(float f) {
    uint32_t r; asm("cvt.rna.tf32.f32 %0, %1;" : "=r"(r) : "f"(f)); return r;
}

// ---------------------------------------------------------------------------
// Kernel 1: x = h @ W1   (M=4096, K=768, N=256).  128x64 tile, 256 threads,
// 8x4 per thread, diagonal-packed FFMA2.  Writes g_x m-major as tf32 (uint4).
// ---------------------------------------------------------------------------
__global__ __launch_bounds__(256) void k_gemm1(const float* __restrict__ A,
                                               const float* __restrict__ W1) {
    __shared__ float As[16][132];   // [k][row]
    __shared__ float Bs[16][68];    // [k][col]
    const int K = E_, N = NBIN * NHID;
    int bx = blockIdx.x;                 // 0..3   (N/64)
    int by = blockIdx.y;                 // 0..31  (M/128)
    int tid = threadIdx.x;
    int tx = tid & 15, ty = tid >> 4;
    int rowBase = by * 128, colBase = bx * 64;

    u64 c[4][4];
#pragma unroll
    for (int i = 0; i < 4; i++)
#pragma unroll
        for (int j = 0; j < 4; j++) c[i][j] = 0;

    for (int k0 = 0; k0 < K; k0 += 16) {
#pragma unroll
        for (int p = 0; p < 8; p++) {          // 128x16 A tile
            int idx = tid + p * 256;
            int r = idx >> 4, cc = idx & 15;
            As[cc][r] = A[(size_t)(rowBase + r) * K + k0 + cc];
        }
#pragma unroll
        for (int p = 0; p < 4; p++) {          // 16x64 B tile
            int idx = tid + p * 256;
            int r = idx >> 6, cc = idx & 63;
            Bs[r][cc] = W1[(size_t)(k0 + r) * N + colBase + cc];
        }
        __syncthreads();
#pragma unroll
        for (int kk = 0; kk < 16; kk++) {
            F4U2 alo, ahi, bv;
            alo.f = *(const float4*)&As[kk][ty * 8];
            ahi.f = *(const float4*)&As[kk][ty * 8 + 4];
            bv.f  = *(const float4*)&Bs[kk][tx * 4];
            u64 ap0 = alo.u[0], ap1 = alo.u[1], ap2 = ahi.u[0], ap3 = ahi.u[1];
            u64 b01 = bv.u[0], b23 = bv.u[1];
            u64 b12 = pk(bv.f.y, bv.f.z);
            u64 b30 = pk(bv.f.w, bv.f.x);
            fma2(c[0][0], ap0, b01); fma2(c[0][1], ap0, b12);
            fma2(c[0][2], ap0, b23); fma2(c[0][3], ap0, b30);
            fma2(c[1][0], ap1, b01); fma2(c[1][1], ap1, b12);
            fma2(c[1][2], ap1, b23); fma2(c[1][3], ap1, b30);
            fma2(c[2][0], ap2, b01); fma2(c[2][1], ap2, b12);
            fma2(c[2][2], ap2, b23); fma2(c[2][3], ap2, b30);
            fma2(c[3][0], ap3, b01); fma2(c[3][1], ap3, b12);
            fma2(c[3][2], ap3, b23); fma2(c[3][3], ap3, b30);
        }
        __syncthreads();
    }

    float o[8][4];
#pragma unroll
    for (int rp = 0; rp < 4; rp++) {
        upk(c[rp][0], o[2*rp][0], o[2*rp+1][1]);
        upk(c[rp][1], o[2*rp][1], o[2*rp+1][2]);
        upk(c[rp][2], o[2*rp][2], o[2*rp+1][3]);
        upk(c[rp][3], o[2*rp][3], o[2*rp+1][0]);
    }
    // cols tx*4..tx*4+3 share one n (tx*4 mod 32 <= 28): one uint4 store each
#pragma unroll
    for (int rr = 0; rr < 8; rr++) {
        size_t row = (size_t)(rowBase + ty * 8 + rr);
        int col0 = colBase + tx * 4;
        int n = col0 >> 5, hh = col0 & 31;
        uint4 q = make_uint4(to_tf32(o[rr][0]), to_tf32(o[rr][1]),
                             to_tf32(o[rr][2]), to_tf32(o[rr][3]));
        *(uint4*)&g_x[(row * 8 + n) * 32 + hh] = q;
    }
}

// ---------------------------------------------------------------------------
// Kernel 2a: seed scan, 16-row granularity.  grid (vb=5, b=4), 256 threads.
// ---------------------------------------------------------------------------
__global__ __launch_bounds__(256) void k_seed(const int* __restrict__ targets) {
    __shared__ int tg[L_];
    int b = blockIdx.y;
    int v = blockIdx.x * 256 + threadIdx.x;
    for (int i = threadIdx.x; i < L_; i += 256)
        tg[i] = targets[(size_t)b * L_ + i];
    __syncthreads();

    int* seed = g_seed + (size_t)b * 64 * V_;
    int nxt = L_;
#pragma unroll 1
    for (int ch = 63; ch >= 0; --ch) {
        seed[(size_t)ch * V_ + v] = nxt;   // occurrences at index >= (ch+1)*16
#pragma unroll
        for (int ii = 15; ii >= 0; --ii) {
            int i = ch * 16 + ii;
            if (tg[i] == v) nxt = i;
        }
    }
}

// ---------------------------------------------------------------------------
// Kernel 2b: tte + mask writer.  grid (chunk=64, b=4), 320 threads,
// 4 consecutive v per thread, 16 rows per block; STG.128 only.
// Special case (scatter semantics): token_index[b, i>=1, v=0] = 0.
// ---------------------------------------------------------------------------
__global__ __launch_bounds__(320) void k_tte_write(const int* __restrict__ targets,
                                                   const float* __restrict__ age,
                                                   const float* __restrict__ targets_age,
                                                   float* __restrict__ out) {
    __shared__ float ta[L_];
    __shared__ float ag_s[16];
    __shared__ int   tg_s[16];

    int b     = blockIdx.y;
    int chunk = blockIdx.x;          // 0..63
    int i0    = chunk * 16;
    int tid   = threadIdx.x;
    int v0    = 4 * tid;             // 0..1276

    if (tid < 256)
        ((float4*)ta)[tid] = ((const float4*)(targets_age + (size_t)b * L_))[tid];
    if (tid < 16) {
        ag_s[tid] = age[(size_t)b * L_ + i0 + tid];
        tg_s[tid] = targets[(size_t)b * L_ + i0 + tid];
    }
    __syncthreads();

    int4 sd = *(const int4*)&g_seed[((size_t)b * 64 + chunk) * V_ + v0];
    int nxt[4] = {sd.x, sd.y, sd.z, sd.w};

    float* out_tte  = out + TTE_OFF  + (size_t)b * L_ * V_;
    float* out_mask = out + MASK_OFF + (size_t)b * L_ * NBIN * V_;
    bool isv0 = (v0 == 0);

#pragma unroll 1
    for (int ii = 15; ii >= 0; --ii) {
        int i = i0 + ii;
        int t = tg_s[ii];
#pragma unroll
        for (int k = 0; k < 4; k++)
            if (t == v0 + k) nxt[k] = i;

        float a = ag_s[ii];
        float tt[4]; bool ne[4];
#pragma unroll
        for (int k = 0; k < 4; k++) {
            int idx = nxt[k];
            if (isv0 && k == 0 && i >= 1) idx = 0;
            ne[k] = (idx == L_);
            tt[k] = ta[ne[k] ? (L_ - 1) : idx] - a;
        }
        *(float4*)&out_tte[(size_t)i * V_ + v0] = make_float4(tt[0], tt[1], tt[2], tt[3]);

        size_t mbase = (size_t)i * NBIN * V_ + v0;
#pragma unroll
        for (int n = 0; n < NBIN; n++) {
            float lo = 1.25f * n;
            float hi = lo + 1.25f;
            float4 m;
            m.x = ((tt[0] >= lo && tt[0] < hi) || ne[0]) ? 1.0f : 0.0f;
            m.y = ((tt[1] >= lo && tt[1] < hi) || ne[1]) ? 1.0f : 0.0f;
            m.z = ((tt[2] >= lo && tt[2] < hi) || ne[2]) ? 1.0f : 0.0f;
            m.w = ((tt[3] >= lo && tt[3] < hi) || ne[3]) ? 1.0f : 0.0f;
            *(float4*)&out_mask[mbase + (size_t)n * V_] = m;
        }
    }
}

// ---------------------------------------------------------------------------
// Kernel 3: logits GEMM via mma.sync tf32 (HMMA tensor path, no 'a' feature).
// M=32768, N=1280, K=32.  Block 256 thr, tile 128m x 64v; warp tile 32m x 32v
// = 2x4 m16n8k8 tiles x 4 k-steps.  fp32 accum.  C[m][v] IS logits layout.
// ---------------------------------------------------------------------------
__global__ __launch_bounds__(256) void k_gemm2m(const float* __restrict__ W2,
                                                float* __restrict__ out) {
    __shared__ uint32_t As[128][36];   // pad 36: frag reads conflict-free
    __shared__ uint32_t Bs[32][72];    // pad 72: bank = 8*l4+g, all distinct
    int tid = threadIdx.x;
    int lane = tid & 31, wid = tid >> 5;
    int g = lane >> 2, l4 = lane & 3;
    int v0 = blockIdx.x * 64;          // 0..19
    int m0 = blockIdx.y * 128;         // 0..255
    int wm = wid & 3, wv = wid >> 2;   // warp tile coords

    // A tile: g_x rows m0..m0+127 (contiguous 16KB, tf32 already)
    const uint4* xsrc = (const uint4*)(g_x + (size_t)m0 * 32);
#pragma unroll
    for (int p = 0; p < 4; p++) {
        int idx = tid + p * 256;           // 1024 uint4
        uint4 q = xsrc[idx];
        int row = idx >> 3, c4 = (idx & 7) << 2;
        *(uint4*)&As[row][c4] = q;
    }
    // B tile: 32h x 64v, convert to tf32
#pragma unroll
    for (int p = 0; p < 8; p++) {
        int idx = tid + p * 256;           // 2048 elems
        int hh = idx >> 6, vv = idx & 63;
        Bs[hh][vv] = to_tf32(W2[(size_t)hh * V_ + v0 + vv]);
    }
    __syncthreads();

    float c[2][4][4];
#pragma unroll
    for (int mt = 0; mt < 2; mt++)
#pragma unroll
        for (int vt = 0; vt < 4; vt++)
#pragma unroll
            for (int q = 0; q < 4; q++) c[mt][vt][q] = 0.0f;

#pragma unroll
    for (int k = 0; k < 4; k++) {
        int kk = k * 8;
        uint32_t a[2][4], b[4][2];
#pragma unroll
        for (int mt = 0; mt < 2; mt++) {
            int rb = wm * 32 + mt * 16;
            a[mt][0] = As[rb + g][kk + l4];
            a[mt][1] = As[rb + g + 8][kk + l4];
            a[mt][2] = As[rb + g][kk + l4 + 4];
            a[mt][3] = As[rb + g + 8][kk + l4 + 4];
        }
#pragma unroll
        for (int vt = 0; vt < 4; vt++) {
            int cb = wv * 32 + vt * 8 + g;
            b[vt][0] = Bs[kk + l4][cb];
            b[vt][1] = Bs[kk + l4 + 4][cb];
        }
#pragma unroll
        for (int mt = 0; mt < 2; mt++)
#pragma unroll
            for (int vt = 0; vt < 4; vt++)
                asm volatile(
                    "mma.sync.aligned.m16n8k8.row.col.f32.tf32.tf32.f32 "
                    "{%0,%1,%2,%3}, {%4,%5,%6,%7}, {%8,%9}, {%0,%1,%2,%3};"
                    : "+f"(c[mt][vt][0]), "+f"(c[mt][vt][1]),
                      "+f"(c[mt][vt][2]), "+f"(c[mt][vt][3])
                    : "r"(a[mt][0]), "r"(a[mt][1]), "r"(a[mt][2]), "r"(a[mt][3]),
                      "r"(b[vt][0]), "r"(b[vt][1]));
    }

    // Epilogue: c0,c1 -> (row g, cols 2*l4..+1); c2,c3 -> row g+8
#pragma unroll
    for (int mt = 0; mt < 2; mt++) {
        int r0 = m0 + wm * 32 + mt * 16 + g;
#pragma unroll
        for (int vt = 0; vt < 4; vt++) {
            int cc = v0 + wv * 32 + vt * 8 + 2 * l4;
            *(float2*)&out[(size_t)r0 * V_ + cc] =
                make_float2(c[mt][vt][0], c[mt][vt][1]);
            *(float2*)&out[(size_t)(r0 + 8) * V_ + cc] =
                make_float2(c[mt][vt][2], c[mt][vt][3]);
        }
    }
}

// ---------------------------------------------------------------------------
static cudaStream_t g_s2;
static cudaEvent_t g_e1, g_e2;
static struct StreamInit {
    StreamInit() {
        cudaStreamCreateWithFlags(&g_s2, cudaStreamNonBlocking);
        cudaEventCreateWithFlags(&g_e1, cudaEventDisableTiming);
        cudaEventCreateWithFlags(&g_e2, cudaEventDisableTiming);
    }
} g_stream_init;

extern "C" void kernel_launch(void* const* d_in, const int* in_sizes, int n_in,
                              void* d_out, int out_size) {
    const float* h       = (const float*)d_in[0];  // (B,L,768)
    const float* age     = (const float*)d_in[1];  // (B,L)
    const float* tage    = (const float*)d_in[2];  // (B,L)
    const int*   targets = (const int*)d_in[4];    // (B,L) int32
    const float* W1      = (const float*)d_in[5];  // (768,256)
    const float* W2      = (const float*)d_in[6];  // (32,1280)
    float* out = (float*)d_out;

    // Fork: seed -> tte_write on stream 2; gemm1 -> gemm2 on stream 0.
    cudaEventRecord(g_e1, 0);
    cudaStreamWaitEvent(g_s2, g_e1, 0);
    k_seed<<<dim3(5, B_), 256, 0, g_s2>>>(targets);
    k_tte_write<<<dim3(64, B_), 320, 0, g_s2>>>(targets, age, tage, out);
    cudaEventRecord(g_e2, g_s2);

    k_gemm1<<<dim3(4, 32), 256>>>(h, W1);
    k_gemm2m<<<dim3(20, 256), 256>>>(W2, out);
    cudaStreamWaitEvent(0, g_e2, 0);
}

// round 11
// speedup vs baseline: 1.4230x; 1.2514x over previous
#include <cuda_runtime.h>
#include <cstdint>

// Problem constants
#define B_    4
#define L_    1024
#define V_    1280
#define E_    768
#define NBIN  8
#define NHID  32

// Output layout: concat(logits[B,L,8,V], tte[B,L,V], mask[B,L,8,V]) fp32
#define TTE_OFF    ((size_t)B_ * L_ * NBIN * V_)                 // 41943040
#define MASK_OFF   (TTE_OFF + (size_t)B_ * L_ * V_)              // 47185920

// Scratch: x = h @ W1, stored m-major as tf32 bit patterns:
// g_x[m*32 + h], m = (b*L+l)*8 + n
__device__ uint32_t g_x[(size_t)B_ * L_ * NBIN * NHID];
// Seed table (16-row granularity): g_seed[b][chunk][v] = next occurrence
// index of v at position >= (chunk+1)*16 ; chunk in [0,64)
__device__ int g_seed[(size_t)B_ * 64 * V_];

typedef unsigned long long u64;

__device__ __forceinline__ uint32_t to_tf32(float f) {
    uint32_t r; asm("cvt.rna.tf32.f32 %0, %1;" : "=r"(r) : "f"(f)); return r;
}

// ---------------------------------------------------------------------------
// Kernel 1: x = h @ W1 via mma.sync tf32 with 3-term split (near-fp32 exact).
// M=4096, N=256, K=768.  Block 128m x 64n, 256 thr, warp tile 32x32,
// K-chunks of 32.  Epilogue writes g_x m-major tf32.
// ---------------------------------------------------------------------------
__global__ __launch_bounds__(256) void k_gemm1t(const float* __restrict__ A,
                                                const float* __restrict__ W1) {
    __shared__ uint32_t Ah[128][36], Al[128][36];   // pad 36: conflict-free
    __shared__ uint32_t Bh[32][72],  Bl[32][72];    // pad 72: conflict-free
    int tid = threadIdx.x;
    int lane = tid & 31, wid = tid >> 5;
    int g = lane >> 2, l4 = lane & 3;
    int colBase = blockIdx.x * 64;      // 0..3
    int rowBase = blockIdx.y * 128;     // 0..31
    int wm = wid & 3, wv = wid >> 2;

    float c[2][4][4];
#pragma unroll
    for (int mt = 0; mt < 2; mt++)
#pragma unroll
        for (int vt = 0; vt < 4; vt++)
#pragma unroll
            for (int q = 0; q < 4; q++) c[mt][vt][q] = 0.0f;

    for (int k0 = 0; k0 < E_; k0 += 32) {
        // A chunk: 128 x 32 fp32 -> hi/lo tf32
#pragma unroll
        for (int p = 0; p < 4; p++) {
            int idx = tid + p * 256;        // 1024 float4
            int r = idx >> 3, c4 = (idx & 7) << 2;
            float4 v = *(const float4*)&A[(size_t)(rowBase + r) * E_ + k0 + c4];
            uint32_t hx = to_tf32(v.x), hy = to_tf32(v.y),
                     hz = to_tf32(v.z), hw = to_tf32(v.w);
            Ah[r][c4+0] = hx; Ah[r][c4+1] = hy; Ah[r][c4+2] = hz; Ah[r][c4+3] = hw;
            Al[r][c4+0] = to_tf32(v.x - __uint_as_float(hx));
            Al[r][c4+1] = to_tf32(v.y - __uint_as_float(hy));
            Al[r][c4+2] = to_tf32(v.z - __uint_as_float(hz));
            Al[r][c4+3] = to_tf32(v.w - __uint_as_float(hw));
        }
        // B chunk: 32 x 64 fp32 -> hi/lo tf32
#pragma unroll
        for (int p = 0; p < 2; p++) {
            int idx = tid + p * 256;        // 512 float4
            int kr = idx >> 4, c4 = (idx & 15) << 2;
            float4 v = *(const float4*)&W1[(size_t)(k0 + kr) * 256 + colBase + c4];
            uint32_t hx = to_tf32(v.x), hy = to_tf32(v.y),
                     hz = to_tf32(v.z), hw = to_tf32(v.w);
            Bh[kr][c4+0] = hx; Bh[kr][c4+1] = hy; Bh[kr][c4+2] = hz; Bh[kr][c4+3] = hw;
            Bl[kr][c4+0] = to_tf32(v.x - __uint_as_float(hx));
            Bl[kr][c4+1] = to_tf32(v.y - __uint_as_float(hy));
            Bl[kr][c4+2] = to_tf32(v.z - __uint_as_float(hz));
            Bl[kr][c4+3] = to_tf32(v.w - __uint_as_float(hw));
        }
        __syncthreads();

#pragma unroll
        for (int ks = 0; ks < 4; ks++) {
            int kk = ks * 8;
            uint32_t ah[2][4], al[2][4], bh[4][2], bl[4][2];
#pragma unroll
            for (int mt = 0; mt < 2; mt++) {
                int rb = wm * 32 + mt * 16;
                ah[mt][0] = Ah[rb + g][kk + l4];
                ah[mt][1] = Ah[rb + g + 8][kk + l4];
                ah[mt][2] = Ah[rb + g][kk + l4 + 4];
                ah[mt][3] = Ah[rb + g + 8][kk + l4 + 4];
                al[mt][0] = Al[rb + g][kk + l4];
                al[mt][1] = Al[rb + g + 8][kk + l4];
                al[mt][2] = Al[rb + g][kk + l4 + 4];
                al[mt][3] = Al[rb + g + 8][kk + l4 + 4];
            }
#pragma unroll
            for (int vt = 0; vt < 4; vt++) {
                int cb = wv * 32 + vt * 8 + g;
                bh[vt][0] = Bh[kk + l4][cb];
                bh[vt][1] = Bh[kk + l4 + 4][cb];
                bl[vt][0] = Bl[kk + l4][cb];
                bl[vt][1] = Bl[kk + l4 + 4][cb];
            }
#pragma unroll
            for (int mt = 0; mt < 2; mt++)
#pragma unroll
                for (int vt = 0; vt < 4; vt++) {
                    asm volatile(
                        "mma.sync.aligned.m16n8k8.row.col.f32.tf32.tf32.f32 "
                        "{%0,%1,%2,%3}, {%4,%5,%6,%7}, {%8,%9}, {%0,%1,%2,%3};"
                        : "+f"(c[mt][vt][0]), "+f"(c[mt][vt][1]),
                          "+f"(c[mt][vt][2]), "+f"(c[mt][vt][3])
                        : "r"(ah[mt][0]), "r"(ah[mt][1]), "r"(ah[mt][2]), "r"(ah[mt][3]),
                          "r"(bh[vt][0]), "r"(bh[vt][1]));
                    asm volatile(
                        "mma.sync.aligned.m16n8k8.row.col.f32.tf32.tf32.f32 "
                        "{%0,%1,%2,%3}, {%4,%5,%6,%7}, {%8,%9}, {%0,%1,%2,%3};"
                        : "+f"(c[mt][vt][0]), "+f"(c[mt][vt][1]),
                          "+f"(c[mt][vt][2]), "+f"(c[mt][vt][3])
                        : "r"(ah[mt][0]), "r"(ah[mt][1]), "r"(ah[mt][2]), "r"(ah[mt][3]),
                          "r"(bl[vt][0]), "r"(bl[vt][1]));
                    asm volatile(
                        "mma.sync.aligned.m16n8k8.row.col.f32.tf32.tf32.f32 "
                        "{%0,%1,%2,%3}, {%4,%5,%6,%7}, {%8,%9}, {%0,%1,%2,%3};"
                        : "+f"(c[mt][vt][0]), "+f"(c[mt][vt][1]),
                          "+f"(c[mt][vt][2]), "+f"(c[mt][vt][3])
                        : "r"(al[mt][0]), "r"(al[mt][1]), "r"(al[mt][2]), "r"(al[mt][3]),
                          "r"(bh[vt][0]), "r"(bh[vt][1]));
                }
        }
        __syncthreads();
    }

    // Epilogue: write x as tf32 to g_x m-major.
    // col = colBase + wv*32 + vt*8 + 2*l4 ; n = col>>5 fixed per warp.
    int n = (colBase >> 5) + wv;
#pragma unroll
    for (int mt = 0; mt < 2; mt++) {
        int r0 = rowBase + wm * 32 + mt * 16 + g;
#pragma unroll
        for (int vt = 0; vt < 4; vt++) {
            int hh = vt * 8 + 2 * l4;
            uint2 q0 = make_uint2(to_tf32(c[mt][vt][0]), to_tf32(c[mt][vt][1]));
            uint2 q1 = make_uint2(to_tf32(c[mt][vt][2]), to_tf32(c[mt][vt][3]));
            *(uint2*)&g_x[((size_t)r0 * 8 + n) * 32 + hh] = q0;
            *(uint2*)&g_x[((size_t)(r0 + 8) * 8 + n) * 32 + hh] = q1;
        }
    }
}

// ---------------------------------------------------------------------------
// Kernel 2a: seed scan, 16-row granularity.  grid (vb=5, b=4), 256 threads.
// ---------------------------------------------------------------------------
__global__ __launch_bounds__(256) void k_seed(const int* __restrict__ targets) {
    __shared__ int tg[L_];
    int b = blockIdx.y;
    int v = blockIdx.x * 256 + threadIdx.x;
    for (int i = threadIdx.x; i < L_; i += 256)
        tg[i] = targets[(size_t)b * L_ + i];
    __syncthreads();

    int* seed = g_seed + (size_t)b * 64 * V_;
    int nxt = L_;
#pragma unroll 1
    for (int ch = 63; ch >= 0; --ch) {
        seed[(size_t)ch * V_ + v] = nxt;   // occurrences at index >= (ch+1)*16
#pragma unroll
        for (int ii = 15; ii >= 0; --ii) {
            int i = ch * 16 + ii;
            if (tg[i] == v) nxt = i;
        }
    }
}

// ---------------------------------------------------------------------------
// Kernel 2b: tte + mask writer.  grid (chunk=64, b=4), 320 threads,
// 4 consecutive v per thread, 16 rows per block; STG.128 only.
// Special case (scatter semantics): token_index[b, i>=1, v=0] = 0.
// ---------------------------------------------------------------------------
__global__ __launch_bounds__(320) void k_tte_write(const int* __restrict__ targets,
                                                   const float* __restrict__ age,
                                                   const float* __restrict__ targets_age,
                                                   float* __restrict__ out) {
    __shared__ float ta[L_];
    __shared__ float ag_s[16];
    __shared__ int   tg_s[16];

    int b     = blockIdx.y;
    int chunk = blockIdx.x;          // 0..63
    int i0    = chunk * 16;
    int tid   = threadIdx.x;
    int v0    = 4 * tid;             // 0..1276

    if (tid < 256)
        ((float4*)ta)[tid] = ((const float4*)(targets_age + (size_t)b * L_))[tid];
    if (tid < 16) {
        ag_s[tid] = age[(size_t)b * L_ + i0 + tid];
        tg_s[tid] = targets[(size_t)b * L_ + i0 + tid];
    }
    __syncthreads();

    int4 sd = *(const int4*)&g_seed[((size_t)b * 64 + chunk) * V_ + v0];
    int nxt[4] = {sd.x, sd.y, sd.z, sd.w};

    float* out_tte  = out + TTE_OFF  + (size_t)b * L_ * V_;
    float* out_mask = out + MASK_OFF + (size_t)b * L_ * NBIN * V_;
    bool isv0 = (v0 == 0);

#pragma unroll 1
    for (int ii = 15; ii >= 0; --ii) {
        int i = i0 + ii;
        int t = tg_s[ii];
#pragma unroll
        for (int k = 0; k < 4; k++)
            if (t == v0 + k) nxt[k] = i;

        float a = ag_s[ii];
        float tt[4]; bool ne[4];
#pragma unroll
        for (int k = 0; k < 4; k++) {
            int idx = nxt[k];
            if (isv0 && k == 0 && i >= 1) idx = 0;
            ne[k] = (idx == L_);
            tt[k] = ta[ne[k] ? (L_ - 1) : idx] - a;
        }
        *(float4*)&out_tte[(size_t)i * V_ + v0] = make_float4(tt[0], tt[1], tt[2], tt[3]);

        size_t mbase = (size_t)i * NBIN * V_ + v0;
#pragma unroll
        for (int n = 0; n < NBIN; n++) {
            float lo = 1.25f * n;
            float hi = lo + 1.25f;
            float4 m;
            m.x = ((tt[0] >= lo && tt[0] < hi) || ne[0]) ? 1.0f : 0.0f;
            m.y = ((tt[1] >= lo && tt[1] < hi) || ne[1]) ? 1.0f : 0.0f;
            m.z = ((tt[2] >= lo && tt[2] < hi) || ne[2]) ? 1.0f : 0.0f;
            m.w = ((tt[3] >= lo && tt[3] < hi) || ne[3]) ? 1.0f : 0.0f;
            *(float4*)&out_mask[mbase + (size_t)n * V_] = m;
        }
    }
}

// ---------------------------------------------------------------------------
// Kernel 3: logits GEMM via mma.sync tf32 (validated in R10).
// M=32768, N=1280, K=32.  Block 256 thr, tile 128m x 64v; warp tile 32m x 32v.
// ---------------------------------------------------------------------------
__global__ __launch_bounds__(256) void k_gemm2m(const float* __restrict__ W2,
                                                float* __restrict__ out) {
    __shared__ uint32_t As[128][36];   // pad 36: frag reads conflict-free
    __shared__ uint32_t Bs[32][72];    // pad 72: frag reads conflict-free
    int tid = threadIdx.x;
    int lane = tid & 31, wid = tid >> 5;
    int g = lane >> 2, l4 = lane & 3;
    int v0 = blockIdx.x * 64;          // 0..19
    int m0 = blockIdx.y * 128;         // 0..255
    int wm = wid & 3, wv = wid >> 2;

    const uint4* xsrc = (const uint4*)(g_x + (size_t)m0 * 32);
#pragma unroll
    for (int p = 0; p < 4; p++) {
        int idx = tid + p * 256;           // 1024 uint4
        uint4 q = xsrc[idx];
        int row = idx >> 3, c4 = (idx & 7) << 2;
        *(uint4*)&As[row][c4] = q;
    }
#pragma unroll
    for (int p = 0; p < 8; p++) {
        int idx = tid + p * 256;           // 2048 elems
        int hh = idx >> 6, vv = idx & 63;
        Bs[hh][vv] = to_tf32(W2[(size_t)hh * V_ + v0 + vv]);
    }
    __syncthreads();

    float c[2][4][4];
#pragma unroll
    for (int mt = 0; mt < 2; mt++)
#pragma unroll
        for (int vt = 0; vt < 4; vt++)
#pragma unroll
            for (int q = 0; q < 4; q++) c[mt][vt][q] = 0.0f;

#pragma unroll
    for (int k = 0; k < 4; k++) {
        int kk = k * 8;
        uint32_t a[2][4], b[4][2];
#pragma unroll
        for (int mt = 0; mt < 2; mt++) {
            int rb = wm * 32 + mt * 16;
            a[mt][0] = As[rb + g][kk + l4];
            a[mt][1] = As[rb + g + 8][kk + l4];
            a[mt][2] = As[rb + g][kk + l4 + 4];
            a[mt][3] = As[rb + g + 8][kk + l4 + 4];
        }
#pragma unroll
        for (int vt = 0; vt < 4; vt++) {
            int cb = wv * 32 + vt * 8 + g;
            b[vt][0] = Bs[kk + l4][cb];
            b[vt][1] = Bs[kk + l4 + 4][cb];
        }
#pragma unroll
        for (int mt = 0; mt < 2; mt++)
#pragma unroll
            for (int vt = 0; vt < 4; vt++)
                asm volatile(
                    "mma.sync.aligned.m16n8k8.row.col.f32.tf32.tf32.f32 "
                    "{%0,%1,%2,%3}, {%4,%5,%6,%7}, {%8,%9}, {%0,%1,%2,%3};"
                    : "+f"(c[mt][vt][0]), "+f"(c[mt][vt][1]),
                      "+f"(c[mt][vt][2]), "+f"(c[mt][vt][3])
                    : "r"(a[mt][0]), "r"(a[mt][1]), "r"(a[mt][2]), "r"(a[mt][3]),
                      "r"(b[vt][0]), "r"(b[vt][1]));
    }

#pragma unroll
    for (int mt = 0; mt < 2; mt++) {
        int r0 = m0 + wm * 32 + mt * 16 + g;
#pragma unroll
        for (int vt = 0; vt < 4; vt++) {
            int cc = v0 + wv * 32 + vt * 8 + 2 * l4;
            *(float2*)&out[(size_t)r0 * V_ + cc] =
                make_float2(c[mt][vt][0], c[mt][vt][1]);
            *(float2*)&out[(size_t)(r0 + 8) * V_ + cc] =
                make_float2(c[mt][vt][2], c[mt][vt][3]);
        }
    }
}

// ---------------------------------------------------------------------------
static cudaStream_t g_s2;
static cudaEvent_t g_e1, g_e2;
static struct StreamInit {
    StreamInit() {
        cudaStreamCreateWithFlags(&g_s2, cudaStreamNonBlocking);
        cudaEventCreateWithFlags(&g_e1, cudaEventDisableTiming);
        cudaEventCreateWithFlags(&g_e2, cudaEventDisableTiming);
    }
} g_stream_init;

extern "C" void kernel_launch(void* const* d_in, const int* in_sizes, int n_in,
                              void* d_out, int out_size) {
    const float* h       = (const float*)d_in[0];  // (B,L,768)
    const float* age     = (const float*)d_in[1];  // (B,L)
    const float* tage    = (const float*)d_in[2];  // (B,L)
    const int*   targets = (const int*)d_in[4];    // (B,L) int32
    const float* W1      = (const float*)d_in[5];  // (768,256)
    const float* W2      = (const float*)d_in[6];  // (32,1280)
    float* out = (float*)d_out;

    // Fork: seed -> tte_write on stream 2; gemm1 -> gemm2 on stream 0.
    cudaEventRecord(g_e1, 0);
    cudaStreamWaitEvent(g_s2, g_e1, 0);
    k_seed<<<dim3(5, B_), 256, 0, g_s2>>>(targets);
    k_tte_write<<<dim3(64, B_), 320, 0, g_s2>>>(targets, age, tage, out);
    cudaEventRecord(g_e2, g_s2);

    k_gemm1t<<<dim3(4, 32), 256>>>(h, W1);
    k_gemm2m<<<dim3(20, 256), 256>>>(W2, out);
    cudaStreamWaitEvent(0, g_e2, 0);
}

// round 12
// speedup vs baseline: 1.5747x; 1.1066x over previous
#include <cuda_runtime.h>
#include <cstdint>

// Problem constants
#define B_    4
#define L_    1024
#define V_    1280
#define E_    768
#define NBIN  8
#define NHID  32

// Output layout: concat(logits[B,L,8,V], tte[B,L,V], mask[B,L,8,V]) fp32
#define TTE_OFF    ((size_t)B_ * L_ * NBIN * V_)                 // 41943040
#define MASK_OFF   (TTE_OFF + (size_t)B_ * L_ * V_)              // 47185920

// Scratch: x = h @ W1, stored m-major as tf32 bit patterns:
// g_x[m*32 + h], m = (b*L+l)*8 + n
__device__ uint32_t g_x[(size_t)B_ * L_ * NBIN * NHID];
// Seed table (16-row granularity): g_seed[b][chunk][v] = next occurrence
// index of v at position >= (chunk+1)*16 ; chunk in [0,64)
__device__ int g_seed[(size_t)B_ * 64 * V_];

typedef unsigned long long u64;

__device__ __forceinline__ uint32_t to_tf32(float f) {
    uint32_t r; asm("cvt.rna.tf32.f32 %0, %1;" : "=r"(r) : "f"(f)); return r;
}

// ---------------------------------------------------------------------------
// Kernel 1: x = h @ W1 via mma.sync tf32, 3-term split (near-fp32 exact).
// M=4096, N=256, K=768.  Retiled for occupancy: block 64m x 32n, 128 thr,
// 4 warps (2wm x 2wv), warp tile 32m x 16n, K-chunks of 32.
// Grid (8, 64) = 512 blocks (was 128 at <1 block/SM).
// ---------------------------------------------------------------------------
__global__ __launch_bounds__(128) void k_gemm1t(const float* __restrict__ A,
                                                const float* __restrict__ W1) {
    __shared__ uint32_t Ah[64][36], Al[64][36];   // pad 36: conflict-free
    __shared__ uint32_t Bh[32][40], Bl[32][40];   // pad 40: conflict-free
    int tid = threadIdx.x;
    int lane = tid & 31, wid = tid >> 5;
    int g = lane >> 2, l4 = lane & 3;
    int colBase = blockIdx.x * 32;      // 0..7
    int rowBase = blockIdx.y * 64;      // 0..63
    int wm = wid & 1, wv = wid >> 1;    // 2 m-warps x 2 n-warps

    float c[2][2][4];
#pragma unroll
    for (int mt = 0; mt < 2; mt++)
#pragma unroll
        for (int vt = 0; vt < 2; vt++)
#pragma unroll
            for (int q = 0; q < 4; q++) c[mt][vt][q] = 0.0f;

    for (int k0 = 0; k0 < E_; k0 += 32) {
        // A chunk: 64 x 32 fp32 -> hi/lo tf32  (512 float4, 4 per thread)
#pragma unroll
        for (int p = 0; p < 4; p++) {
            int idx = tid + p * 128;
            int r = idx >> 3, c4 = (idx & 7) << 2;
            float4 v = *(const float4*)&A[(size_t)(rowBase + r) * E_ + k0 + c4];
            uint32_t hx = to_tf32(v.x), hy = to_tf32(v.y),
                     hz = to_tf32(v.z), hw = to_tf32(v.w);
            Ah[r][c4+0] = hx; Ah[r][c4+1] = hy; Ah[r][c4+2] = hz; Ah[r][c4+3] = hw;
            Al[r][c4+0] = to_tf32(v.x - __uint_as_float(hx));
            Al[r][c4+1] = to_tf32(v.y - __uint_as_float(hy));
            Al[r][c4+2] = to_tf32(v.z - __uint_as_float(hz));
            Al[r][c4+3] = to_tf32(v.w - __uint_as_float(hw));
        }
        // B chunk: 32 x 32 fp32 -> hi/lo tf32  (256 float4, 2 per thread)
#pragma unroll
        for (int p = 0; p < 2; p++) {
            int idx = tid + p * 128;
            int kr = idx >> 3, c4 = (idx & 7) << 2;
            float4 v = *(const float4*)&W1[(size_t)(k0 + kr) * 256 + colBase + c4];
            uint32_t hx = to_tf32(v.x), hy = to_tf32(v.y),
                     hz = to_tf32(v.z), hw = to_tf32(v.w);
            Bh[kr][c4+0] = hx; Bh[kr][c4+1] = hy; Bh[kr][c4+2] = hz; Bh[kr][c4+3] = hw;
            Bl[kr][c4+0] = to_tf32(v.x - __uint_as_float(hx));
            Bl[kr][c4+1] = to_tf32(v.y - __uint_as_float(hy));
            Bl[kr][c4+2] = to_tf32(v.z - __uint_as_float(hz));
            Bl[kr][c4+3] = to_tf32(v.w - __uint_as_float(hw));
        }
        __syncthreads();

#pragma unroll
        for (int ks = 0; ks < 4; ks++) {
            int kk = ks * 8;
            uint32_t ah[2][4], al[2][4], bh[2][2], bl[2][2];
#pragma unroll
            for (int mt = 0; mt < 2; mt++) {
                int rb = wm * 32 + mt * 16;
                ah[mt][0] = Ah[rb + g][kk + l4];
                ah[mt][1] = Ah[rb + g + 8][kk + l4];
                ah[mt][2] = Ah[rb + g][kk + l4 + 4];
                ah[mt][3] = Ah[rb + g + 8][kk + l4 + 4];
                al[mt][0] = Al[rb + g][kk + l4];
                al[mt][1] = Al[rb + g + 8][kk + l4];
                al[mt][2] = Al[rb + g][kk + l4 + 4];
                al[mt][3] = Al[rb + g + 8][kk + l4 + 4];
            }
#pragma unroll
            for (int vt = 0; vt < 2; vt++) {
                int cb = wv * 16 + vt * 8 + g;
                bh[vt][0] = Bh[kk + l4][cb];
                bh[vt][1] = Bh[kk + l4 + 4][cb];
                bl[vt][0] = Bl[kk + l4][cb];
                bl[vt][1] = Bl[kk + l4 + 4][cb];
            }
#pragma unroll
            for (int mt = 0; mt < 2; mt++)
#pragma unroll
                for (int vt = 0; vt < 2; vt++) {
                    asm volatile(
                        "mma.sync.aligned.m16n8k8.row.col.f32.tf32.tf32.f32 "
                        "{%0,%1,%2,%3}, {%4,%5,%6,%7}, {%8,%9}, {%0,%1,%2,%3};"
                        : "+f"(c[mt][vt][0]), "+f"(c[mt][vt][1]),
                          "+f"(c[mt][vt][2]), "+f"(c[mt][vt][3])
                        : "r"(ah[mt][0]), "r"(ah[mt][1]), "r"(ah[mt][2]), "r"(ah[mt][3]),
                          "r"(bh[vt][0]), "r"(bh[vt][1]));
                    asm volatile(
                        "mma.sync.aligned.m16n8k8.row.col.f32.tf32.tf32.f32 "
                        "{%0,%1,%2,%3}, {%4,%5,%6,%7}, {%8,%9}, {%0,%1,%2,%3};"
                        : "+f"(c[mt][vt][0]), "+f"(c[mt][vt][1]),
                          "+f"(c[mt][vt][2]), "+f"(c[mt][vt][3])
                        : "r"(ah[mt][0]), "r"(ah[mt][1]), "r"(ah[mt][2]), "r"(ah[mt][3]),
                          "r"(bl[vt][0]), "r"(bl[vt][1]));
                    asm volatile(
                        "mma.sync.aligned.m16n8k8.row.col.f32.tf32.tf32.f32 "
                        "{%0,%1,%2,%3}, {%4,%5,%6,%7}, {%8,%9}, {%0,%1,%2,%3};"
                        : "+f"(c[mt][vt][0]), "+f"(c[mt][vt][1]),
                          "+f"(c[mt][vt][2]), "+f"(c[mt][vt][3])
                        : "r"(al[mt][0]), "r"(al[mt][1]), "r"(al[mt][2]), "r"(al[mt][3]),
                          "r"(bh[vt][0]), "r"(bh[vt][1]));
                }
        }
        __syncthreads();
    }

    // Epilogue: write x as tf32 to g_x m-major.
#pragma unroll
    for (int mt = 0; mt < 2; mt++) {
        int r0 = rowBase + wm * 32 + mt * 16 + g;
#pragma unroll
        for (int vt = 0; vt < 2; vt++) {
            int col = colBase + wv * 16 + vt * 8 + 2 * l4;
            int n = col >> 5, hh = col & 31;
            uint2 q0 = make_uint2(to_tf32(c[mt][vt][0]), to_tf32(c[mt][vt][1]));
            uint2 q1 = make_uint2(to_tf32(c[mt][vt][2]), to_tf32(c[mt][vt][3]));
            *(uint2*)&g_x[((size_t)r0 * 8 + n) * 32 + hh] = q0;
            *(uint2*)&g_x[((size_t)(r0 + 8) * 8 + n) * 32 + hh] = q1;
        }
    }
}

// ---------------------------------------------------------------------------
// Kernel 2a: seed scan, 16-row granularity.  grid (vb=5, b=4), 256 threads.
// ---------------------------------------------------------------------------
__global__ __launch_bounds__(256) void k_seed(const int* __restrict__ targets) {
    __shared__ int tg[L_];
    int b = blockIdx.y;
    int v = blockIdx.x * 256 + threadIdx.x;
    for (int i = threadIdx.x; i < L_; i += 256)
        tg[i] = targets[(size_t)b * L_ + i];
    __syncthreads();

    int* seed = g_seed + (size_t)b * 64 * V_;
    int nxt = L_;
#pragma unroll 1
    for (int ch = 63; ch >= 0; --ch) {
        seed[(size_t)ch * V_ + v] = nxt;   // occurrences at index >= (ch+1)*16
#pragma unroll
        for (int ii = 15; ii >= 0; --ii) {
            int i = ch * 16 + ii;
            if (tg[i] == v) nxt = i;
        }
    }
}

// ---------------------------------------------------------------------------
// Kernel 2b: tte + mask writer.  grid (chunk=64, b=4), 320 threads,
// 4 consecutive v per thread, 16 rows per block; STG.128 only.
// Special case (scatter semantics): token_index[b, i>=1, v=0] = 0.
// ---------------------------------------------------------------------------
__global__ __launch_bounds__(320) void k_tte_write(const int* __restrict__ targets,
                                                   const float* __restrict__ age,
                                                   const float* __restrict__ targets_age,
                                                   float* __restrict__ out) {
    __shared__ float ta[L_];
    __shared__ float ag_s[16];
    __shared__ int   tg_s[16];

    int b     = blockIdx.y;
    int chunk = blockIdx.x;          // 0..63
    int i0    = chunk * 16;
    int tid   = threadIdx.x;
    int v0    = 4 * tid;             // 0..1276

    if (tid < 256)
        ((float4*)ta)[tid] = ((const float4*)(targets_age + (size_t)b * L_))[tid];
    if (tid < 16) {
        ag_s[tid] = age[(size_t)b * L_ + i0 + tid];
        tg_s[tid] = targets[(size_t)b * L_ + i0 + tid];
    }
    __syncthreads();

    int4 sd = *(const int4*)&g_seed[((size_t)b * 64 + chunk) * V_ + v0];
    int nxt[4] = {sd.x, sd.y, sd.z, sd.w};

    float* out_tte  = out + TTE_OFF  + (size_t)b * L_ * V_;
    float* out_mask = out + MASK_OFF + (size_t)b * L_ * NBIN * V_;
    bool isv0 = (v0 == 0);

#pragma unroll 1
    for (int ii = 15; ii >= 0; --ii) {
        int i = i0 + ii;
        int t = tg_s[ii];
#pragma unroll
        for (int k = 0; k < 4; k++)
            if (t == v0 + k) nxt[k] = i;

        float a = ag_s[ii];
        float tt[4]; bool ne[4];
#pragma unroll
        for (int k = 0; k < 4; k++) {
            int idx = nxt[k];
            if (isv0 && k == 0 && i >= 1) idx = 0;
            ne[k] = (idx == L_);
            tt[k] = ta[ne[k] ? (L_ - 1) : idx] - a;
        }
        *(float4*)&out_tte[(size_t)i * V_ + v0] = make_float4(tt[0], tt[1], tt[2], tt[3]);

        size_t mbase = (size_t)i * NBIN * V_ + v0;
#pragma unroll
        for (int n = 0; n < NBIN; n++) {
            float lo = 1.25f * n;
            float hi = lo + 1.25f;
            float4 m;
            m.x = ((tt[0] >= lo && tt[0] < hi) || ne[0]) ? 1.0f : 0.0f;
            m.y = ((tt[1] >= lo && tt[1] < hi) || ne[1]) ? 1.0f : 0.0f;
            m.z = ((tt[2] >= lo && tt[2] < hi) || ne[2]) ? 1.0f : 0.0f;
            m.w = ((tt[3] >= lo && tt[3] < hi) || ne[3]) ? 1.0f : 0.0f;
            *(float4*)&out_mask[mbase + (size_t)n * V_] = m;
        }
    }
}

// ---------------------------------------------------------------------------
// Kernel 3: logits GEMM via mma.sync tf32 (validated in R10/R11).
// M=32768, N=1280, K=32.  Block 256 thr, tile 128m x 64v; warp tile 32m x 32v.
// B fill vectorized (LDG.128/STS.128).
// ---------------------------------------------------------------------------
__global__ __launch_bounds__(256) void k_gemm2m(const float* __restrict__ W2,
                                                float* __restrict__ out) {
    __shared__ uint32_t As[128][36];   // pad 36: frag reads conflict-free
    __shared__ uint32_t Bs[32][72];    // pad 72: frag reads conflict-free
    int tid = threadIdx.x;
    int lane = tid & 31, wid = tid >> 5;
    int g = lane >> 2, l4 = lane & 3;
    int v0 = blockIdx.x * 64;          // 0..19
    int m0 = blockIdx.y * 128;         // 0..255
    int wm = wid & 3, wv = wid >> 2;

    const uint4* xsrc = (const uint4*)(g_x + (size_t)m0 * 32);
#pragma unroll
    for (int p = 0; p < 4; p++) {
        int idx = tid + p * 256;           // 1024 uint4
        uint4 q = xsrc[idx];
        int row = idx >> 3, c4 = (idx & 7) << 2;
        *(uint4*)&As[row][c4] = q;
    }
    // B tile: 32h x 64v = 512 float4, 2 per thread; convert then STS.128
#pragma unroll
    for (int p = 0; p < 2; p++) {
        int idx = tid + p * 256;           // 512 float4
        int hh = idx >> 4, v4 = (idx & 15) << 2;
        float4 w = *(const float4*)&W2[(size_t)hh * V_ + v0 + v4];
        uint4 q = make_uint4(to_tf32(w.x), to_tf32(w.y), to_tf32(w.z), to_tf32(w.w));
        *(uint4*)&Bs[hh][v4] = q;
    }
    __syncthreads();

    float c[2][4][4];
#pragma unroll
    for (int mt = 0; mt < 2; mt++)
#pragma unroll
        for (int vt = 0; vt < 4; vt++)
#pragma unroll
            for (int q = 0; q < 4; q++) c[mt][vt][q] = 0.0f;

#pragma unroll
    for (int k = 0; k < 4; k++) {
        int kk = k * 8;
        uint32_t a[2][4], b[4][2];
#pragma unroll
        for (int mt = 0; mt < 2; mt++) {
            int rb = wm * 32 + mt * 16;
            a[mt][0] = As[rb + g][kk + l4];
            a[mt][1] = As[rb + g + 8][kk + l4];
            a[mt][2] = As[rb + g][kk + l4 + 4];
            a[mt][3] = As[rb + g + 8][kk + l4 + 4];
        }
#pragma unroll
        for (int vt = 0; vt < 4; vt++) {
            int cb = wv * 32 + vt * 8 + g;
            b[vt][0] = Bs[kk + l4][cb];
            b[vt][1] = Bs[kk + l4 + 4][cb];
        }
#pragma unroll
        for (int mt = 0; mt < 2; mt++)
#pragma unroll
            for (int vt = 0; vt < 4; vt++)
                asm volatile(
                    "mma.sync.aligned.m16n8k8.row.col.f32.tf32.tf32.f32 "
                    "{%0,%1,%2,%3}, {%4,%5,%6,%7}, {%8,%9}, {%0,%1,%2,%3};"
                    : "+f"(c[mt][vt][0]), "+f"(c[mt][vt][1]),
                      "+f"(c[mt][vt][2]), "+f"(c[mt][vt][3])
                    : "r"(a[mt][0]), "r"(a[mt][1]), "r"(a[mt][2]), "r"(a[mt][3]),
                      "r"(b[vt][0]), "r"(b[vt][1]));
    }

#pragma unroll
    for (int mt = 0; mt < 2; mt++) {
        int r0 = m0 + wm * 32 + mt * 16 + g;
#pragma unroll
        for (int vt = 0; vt < 4; vt++) {
            int cc = v0 + wv * 32 + vt * 8 + 2 * l4;
            *(float2*)&out[(size_t)r0 * V_ + cc] =
                make_float2(c[mt][vt][0], c[mt][vt][1]);
            *(float2*)&out[(size_t)(r0 + 8) * V_ + cc] =
                make_float2(c[mt][vt][2], c[mt][vt][3]);
        }
    }
}

// ---------------------------------------------------------------------------
static cudaStream_t g_s2;
static cudaEvent_t g_e1, g_e2;
static struct StreamInit {
    StreamInit() {
        cudaStreamCreateWithFlags(&g_s2, cudaStreamNonBlocking);
        cudaEventCreateWithFlags(&g_e1, cudaEventDisableTiming);
        cudaEventCreateWithFlags(&g_e2, cudaEventDisableTiming);
    }
} g_stream_init;

extern "C" void kernel_launch(void* const* d_in, const int* in_sizes, int n_in,
                              void* d_out, int out_size) {
    const float* h       = (const float*)d_in[0];  // (B,L,768)
    const float* age     = (const float*)d_in[1];  // (B,L)
    const float* tage    = (const float*)d_in[2];  // (B,L)
    const int*   targets = (const int*)d_in[4];    // (B,L) int32
    const float* W1      = (const float*)d_in[5];  // (768,256)
    const float* W2      = (const float*)d_in[6];  // (32,1280)
    float* out = (float*)d_out;

    // Fork: seed -> tte_write on stream 2; gemm1 -> gemm2 on stream 0.
    cudaEventRecord(g_e1, 0);
    cudaStreamWaitEvent(g_s2, g_e1, 0);
    k_seed<<<dim3(5, B_), 256, 0, g_s2>>>(targets);
    k_tte_write<<<dim3(64, B_), 320, 0, g_s2>>>(targets, age, tage, out);
    cudaEventRecord(g_e2, g_s2);

    k_gemm1t<<<dim3(8, 64), 128>>>(h, W1);
    k_gemm2m<<<dim3(20, 256), 256>>>(W2, out);
    cudaStreamWaitEvent(0, g_e2, 0);
}

// round 13
// speedup vs baseline: 1.6925x; 1.0748x over previous
#include <cuda_runtime.h>
#include <cstdint>

// Problem constants
#define B_    4
#define L_    1024
#define V_    1280
#define E_    768
#define NBIN  8
#define NHID  32

// Output layout: concat(logits[B,L,8,V], tte[B,L,V], mask[B,L,8,V]) fp32
#define TTE_OFF    ((size_t)B_ * L_ * NBIN * V_)                 // 41943040
#define MASK_OFF   (TTE_OFF + (size_t)B_ * L_ * V_)              // 47185920

// Scratch: x = h @ W1, stored m-major as tf32 bit patterns:
// g_x[m*32 + h], m = (b*L+l)*8 + n
__device__ uint32_t g_x[(size_t)B_ * L_ * NBIN * NHID];
// Seed table (16-row granularity)
__device__ int g_seed[(size_t)B_ * 64 * V_];
// Precomputed W1 hi/lo tf32 split (768 x 256 each)
__device__ uint32_t g_W1h[E_ * 256];
__device__ uint32_t g_W1l[E_ * 256];

typedef unsigned long long u64;

__device__ __forceinline__ uint32_t to_tf32(float f) {
    uint32_t r; asm("cvt.rna.tf32.f32 %0, %1;" : "=r"(r) : "f"(f)); return r;
}

// ---------------------------------------------------------------------------
// Kernel 0: W1 -> hi/lo tf32 split, once.  49152 float4, grid 192 x 256.
// ---------------------------------------------------------------------------
__global__ __launch_bounds__(256) void k_prep(const float* __restrict__ W1) {
    int i = blockIdx.x * 256 + threadIdx.x;      // 0..49151
    float4 v = ((const float4*)W1)[i];
    uint32_t hx = to_tf32(v.x), hy = to_tf32(v.y),
             hz = to_tf32(v.z), hw = to_tf32(v.w);
    ((uint4*)g_W1h)[i] = make_uint4(hx, hy, hz, hw);
    ((uint4*)g_W1l)[i] = make_uint4(to_tf32(v.x - __uint_as_float(hx)),
                                    to_tf32(v.y - __uint_as_float(hy)),
                                    to_tf32(v.z - __uint_as_float(hz)),
                                    to_tf32(v.w - __uint_as_float(hw)));
}

// ---------------------------------------------------------------------------
// Kernel 1: x = h @ W1 via mma.sync tf32, 3-term split (near-fp32 exact).
// M=4096, N=256, K=768.  Block 64m x 64n, 128 thr, 4 warps (2wm x 2wv),
// warp tile 32m x 32n, K-chunks of 32.  Grid (4, 64) = 256 blocks.
// B comes pre-split from g_W1h/g_W1l (no cvt in loop).
// ---------------------------------------------------------------------------
__global__ __launch_bounds__(128) void k_gemm1t(const float* __restrict__ A) {
    __shared__ uint32_t Ah[64][36], Al[64][36];   // pad 36: banks 4g+l4
    __shared__ uint32_t Bh[32][72], Bl[32][72];   // pad 72: banks 8l4+g
    int tid = threadIdx.x;
    int lane = tid & 31, wid = tid >> 5;
    int g = lane >> 2, l4 = lane & 3;
    int colBase = blockIdx.x * 64;      // 0..3
    int rowBase = blockIdx.y * 64;      // 0..63
    int wm = wid & 1, wv = wid >> 1;    // 2 m-warps x 2 n-warps

    float c[2][4][4];
#pragma unroll
    for (int mt = 0; mt < 2; mt++)
#pragma unroll
        for (int vt = 0; vt < 4; vt++)
#pragma unroll
            for (int q = 0; q < 4; q++) c[mt][vt][q] = 0.0f;

    for (int k0 = 0; k0 < E_; k0 += 32) {
        // A chunk: 64 x 32 fp32 -> hi/lo tf32  (512 float4, 4 per thread)
#pragma unroll
        for (int p = 0; p < 4; p++) {
            int idx = tid + p * 128;
            int r = idx >> 3, c4 = (idx & 7) << 2;
            float4 v = *(const float4*)&A[(size_t)(rowBase + r) * E_ + k0 + c4];
            uint32_t hx = to_tf32(v.x), hy = to_tf32(v.y),
                     hz = to_tf32(v.z), hw = to_tf32(v.w);
            Ah[r][c4+0] = hx; Ah[r][c4+1] = hy; Ah[r][c4+2] = hz; Ah[r][c4+3] = hw;
            Al[r][c4+0] = to_tf32(v.x - __uint_as_float(hx));
            Al[r][c4+1] = to_tf32(v.y - __uint_as_float(hy));
            Al[r][c4+2] = to_tf32(v.z - __uint_as_float(hz));
            Al[r][c4+3] = to_tf32(v.w - __uint_as_float(hw));
        }
        // B chunk: 32 x 64 pre-split tf32 (512 uint4 per buffer, 4 each)
#pragma unroll
        for (int p = 0; p < 4; p++) {
            int idx = tid + p * 128;
            int kr = idx >> 4, c4 = (idx & 15) << 2;
            size_t goff = ((size_t)(k0 + kr) * 256 + colBase + c4) >> 2;
            *(uint4*)&Bh[kr][c4] = ((const uint4*)g_W1h)[goff];
            *(uint4*)&Bl[kr][c4] = ((const uint4*)g_W1l)[goff];
        }
        __syncthreads();

#pragma unroll
        for (int ks = 0; ks < 4; ks++) {
            int kk = ks * 8;
            uint32_t ah[2][4], al[2][4], bh[4][2], bl[4][2];
#pragma unroll
            for (int mt = 0; mt < 2; mt++) {
                int rb = wm * 32 + mt * 16;
                ah[mt][0] = Ah[rb + g][kk + l4];
                ah[mt][1] = Ah[rb + g + 8][kk + l4];
                ah[mt][2] = Ah[rb + g][kk + l4 + 4];
                ah[mt][3] = Ah[rb + g + 8][kk + l4 + 4];
                al[mt][0] = Al[rb + g][kk + l4];
                al[mt][1] = Al[rb + g + 8][kk + l4];
                al[mt][2] = Al[rb + g][kk + l4 + 4];
                al[mt][3] = Al[rb + g + 8][kk + l4 + 4];
            }
#pragma unroll
            for (int vt = 0; vt < 4; vt++) {
                int cb = wv * 32 + vt * 8 + g;
                bh[vt][0] = Bh[kk + l4][cb];
                bh[vt][1] = Bh[kk + l4 + 4][cb];
                bl[vt][0] = Bl[kk + l4][cb];
                bl[vt][1] = Bl[kk + l4 + 4][cb];
            }
#pragma unroll
            for (int mt = 0; mt < 2; mt++)
#pragma unroll
                for (int vt = 0; vt < 4; vt++) {
                    asm volatile(
                        "mma.sync.aligned.m16n8k8.row.col.f32.tf32.tf32.f32 "
                        "{%0,%1,%2,%3}, {%4,%5,%6,%7}, {%8,%9}, {%0,%1,%2,%3};"
                        : "+f"(c[mt][vt][0]), "+f"(c[mt][vt][1]),
                          "+f"(c[mt][vt][2]), "+f"(c[mt][vt][3])
                        : "r"(ah[mt][0]), "r"(ah[mt][1]), "r"(ah[mt][2]), "r"(ah[mt][3]),
                          "r"(bh[vt][0]), "r"(bh[vt][1]));
                    asm volatile(
                        "mma.sync.aligned.m16n8k8.row.col.f32.tf32.tf32.f32 "
                        "{%0,%1,%2,%3}, {%4,%5,%6,%7}, {%8,%9}, {%0,%1,%2,%3};"
                        : "+f"(c[mt][vt][0]), "+f"(c[mt][vt][1]),
                          "+f"(c[mt][vt][2]), "+f"(c[mt][vt][3])
                        : "r"(ah[mt][0]), "r"(ah[mt][1]), "r"(ah[mt][2]), "r"(ah[mt][3]),
                          "r"(bl[vt][0]), "r"(bl[vt][1]));
                    asm volatile(
                        "mma.sync.aligned.m16n8k8.row.col.f32.tf32.tf32.f32 "
                        "{%0,%1,%2,%3}, {%4,%5,%6,%7}, {%8,%9}, {%0,%1,%2,%3};"
                        : "+f"(c[mt][vt][0]), "+f"(c[mt][vt][1]),
                          "+f"(c[mt][vt][2]), "+f"(c[mt][vt][3])
                        : "r"(al[mt][0]), "r"(al[mt][1]), "r"(al[mt][2]), "r"(al[mt][3]),
                          "r"(bh[vt][0]), "r"(bh[vt][1]));
                }
        }
        __syncthreads();
    }

    // Epilogue: write x as tf32 to g_x m-major.
#pragma unroll
    for (int mt = 0; mt < 2; mt++) {
        int r0 = rowBase + wm * 32 + mt * 16 + g;
#pragma unroll
        for (int vt = 0; vt < 4; vt++) {
            int col = colBase + wv * 32 + vt * 8 + 2 * l4;
            int n = col >> 5, hh = col & 31;
            uint2 q0 = make_uint2(to_tf32(c[mt][vt][0]), to_tf32(c[mt][vt][1]));
            uint2 q1 = make_uint2(to_tf32(c[mt][vt][2]), to_tf32(c[mt][vt][3]));
            *(uint2*)&g_x[((size_t)r0 * 8 + n) * 32 + hh] = q0;
            *(uint2*)&g_x[((size_t)(r0 + 8) * 8 + n) * 32 + hh] = q1;
        }
    }
}

// ---------------------------------------------------------------------------
// Kernel 2a: seed scan, 16-row granularity.  grid (vb=5, b=4), 256 threads.
// ---------------------------------------------------------------------------
__global__ __launch_bounds__(256) void k_seed(const int* __restrict__ targets) {
    __shared__ int tg[L_];
    int b = blockIdx.y;
    int v = blockIdx.x * 256 + threadIdx.x;
    for (int i = threadIdx.x; i < L_; i += 256)
        tg[i] = targets[(size_t)b * L_ + i];
    __syncthreads();

    int* seed = g_seed + (size_t)b * 64 * V_;
    int nxt = L_;
#pragma unroll 1
    for (int ch = 63; ch >= 0; --ch) {
        seed[(size_t)ch * V_ + v] = nxt;   // occurrences at index >= (ch+1)*16
#pragma unroll
        for (int ii = 15; ii >= 0; --ii) {
            int i = ch * 16 + ii;
            if (tg[i] == v) nxt = i;
        }
    }
}

// ---------------------------------------------------------------------------
// Kernel 2b: tte + mask writer.  grid (chunk=64, b=4), 320 threads,
// 4 consecutive v per thread, 16 rows per block; STG.128 only.
// Special case (scatter semantics): token_index[b, i>=1, v=0] = 0.
// ---------------------------------------------------------------------------
__global__ __launch_bounds__(320) void k_tte_write(const int* __restrict__ targets,
                                                   const float* __restrict__ age,
                                                   const float* __restrict__ targets_age,
                                                   float* __restrict__ out) {
    __shared__ float ta[L_];
    __shared__ float ag_s[16];
    __shared__ int   tg_s[16];

    int b     = blockIdx.y;
    int chunk = blockIdx.x;          // 0..63
    int i0    = chunk * 16;
    int tid   = threadIdx.x;
    int v0    = 4 * tid;             // 0..1276

    if (tid < 256)
        ((float4*)ta)[tid] = ((const float4*)(targets_age + (size_t)b * L_))[tid];
    if (tid < 16) {
        ag_s[tid] = age[(size_t)b * L_ + i0 + tid];
        tg_s[tid] = targets[(size_t)b * L_ + i0 + tid];
    }
    __syncthreads();

    int4 sd = *(const int4*)&g_seed[((size_t)b * 64 + chunk) * V_ + v0];
    int nxt[4] = {sd.x, sd.y, sd.z, sd.w};

    float* out_tte  = out + TTE_OFF  + (size_t)b * L_ * V_;
    float* out_mask = out + MASK_OFF + (size_t)b * L_ * NBIN * V_;
    bool isv0 = (v0 == 0);

#pragma unroll 1
    for (int ii = 15; ii >= 0; --ii) {
        int i = i0 + ii;
        int t = tg_s[ii];
#pragma unroll
        for (int k = 0; k < 4; k++)
            if (t == v0 + k) nxt[k] = i;

        float a = ag_s[ii];
        float tt[4]; bool ne[4];
#pragma unroll
        for (int k = 0; k < 4; k++) {
            int idx = nxt[k];
            if (isv0 && k == 0 && i >= 1) idx = 0;
            ne[k] = (idx == L_);
            tt[k] = ta[ne[k] ? (L_ - 1) : idx] - a;
        }
        *(float4*)&out_tte[(size_t)i * V_ + v0] = make_float4(tt[0], tt[1], tt[2], tt[3]);

        size_t mbase = (size_t)i * NBIN * V_ + v0;
#pragma unroll
        for (int n = 0; n < NBIN; n++) {
            float lo = 1.25f * n;
            float hi = lo + 1.25f;
            float4 m;
            m.x = ((tt[0] >= lo && tt[0] < hi) || ne[0]) ? 1.0f : 0.0f;
            m.y = ((tt[1] >= lo && tt[1] < hi) || ne[1]) ? 1.0f : 0.0f;
            m.z = ((tt[2] >= lo && tt[2] < hi) || ne[2]) ? 1.0f : 0.0f;
            m.w = ((tt[3] >= lo && tt[3] < hi) || ne[3]) ? 1.0f : 0.0f;
            *(float4*)&out_mask[mbase + (size_t)n * V_] = m;
        }
    }
}

// ---------------------------------------------------------------------------
// Kernel 3: logits GEMM via mma.sync tf32 (validated R10-R12, unchanged).
// M=32768, N=1280, K=32.  Block 256 thr, tile 128m x 64v; warp tile 32m x 32v.
// ---------------------------------------------------------------------------
__global__ __launch_bounds__(256) void k_gemm2m(const float* __restrict__ W2,
                                                float* __restrict__ out) {
    __shared__ uint32_t As[128][36];
    __shared__ uint32_t Bs[32][72];
    int tid = threadIdx.x;
    int lane = tid & 31, wid = tid >> 5;
    int g = lane >> 2, l4 = lane & 3;
    int v0 = blockIdx.x * 64;          // 0..19
    int m0 = blockIdx.y * 128;         // 0..255
    int wm = wid & 3, wv = wid >> 2;

    const uint4* xsrc = (const uint4*)(g_x + (size_t)m0 * 32);
#pragma unroll
    for (int p = 0; p < 4; p++) {
        int idx = tid + p * 256;           // 1024 uint4
        uint4 q = xsrc[idx];
        int row = idx >> 3, c4 = (idx & 7) << 2;
        *(uint4*)&As[row][c4] = q;
    }
#pragma unroll
    for (int p = 0; p < 2; p++) {
        int idx = tid + p * 256;           // 512 float4
        int hh = idx >> 4, v4 = (idx & 15) << 2;
        float4 w = *(const float4*)&W2[(size_t)hh * V_ + v0 + v4];
        uint4 q = make_uint4(to_tf32(w.x), to_tf32(w.y), to_tf32(w.z), to_tf32(w.w));
        *(uint4*)&Bs[hh][v4] = q;
    }
    __syncthreads();

    float c[2][4][4];
#pragma unroll
    for (int mt = 0; mt < 2; mt++)
#pragma unroll
        for (int vt = 0; vt < 4; vt++)
#pragma unroll
            for (int q = 0; q < 4; q++) c[mt][vt][q] = 0.0f;

#pragma unroll
    for (int k = 0; k < 4; k++) {
        int kk = k * 8;
        uint32_t a[2][4], b[4][2];
#pragma unroll
        for (int mt = 0; mt < 2; mt++) {
            int rb = wm * 32 + mt * 16;
            a[mt][0] = As[rb + g][kk + l4];
            a[mt][1] = As[rb + g + 8][kk + l4];
            a[mt][2] = As[rb + g][kk + l4 + 4];
            a[mt][3] = As[rb + g + 8][kk + l4 + 4];
        }
#pragma unroll
        for (int vt = 0; vt < 4; vt++) {
            int cb = wv * 32 + vt * 8 + g;
            b[vt][0] = Bs[kk + l4][cb];
            b[vt][1] = Bs[kk + l4 + 4][cb];
        }
#pragma unroll
        for (int mt = 0; mt < 2; mt++)
#pragma unroll
            for (int vt = 0; vt < 4; vt++)
                asm volatile(
                    "mma.sync.aligned.m16n8k8.row.col.f32.tf32.tf32.f32 "
                    "{%0,%1,%2,%3}, {%4,%5,%6,%7}, {%8,%9}, {%0,%1,%2,%3};"
                    : "+f"(c[mt][vt][0]), "+f"(c[mt][vt][1]),
                      "+f"(c[mt][vt][2]), "+f"(c[mt][vt][3])
                    : "r"(a[mt][0]), "r"(a[mt][1]), "r"(a[mt][2]), "r"(a[mt][3]),
                      "r"(b[vt][0]), "r"(b[vt][1]));
    }

#pragma unroll
    for (int mt = 0; mt < 2; mt++) {
        int r0 = m0 + wm * 32 + mt * 16 + g;
#pragma unroll
        for (int vt = 0; vt < 4; vt++) {
            int cc = v0 + wv * 32 + vt * 8 + 2 * l4;
            *(float2*)&out[(size_t)r0 * V_ + cc] =
                make_float2(c[mt][vt][0], c[mt][vt][1]);
            *(float2*)&out[(size_t)(r0 + 8) * V_ + cc] =
                make_float2(c[mt][vt][2], c[mt][vt][3]);
        }
    }
}

// ---------------------------------------------------------------------------
static cudaStream_t g_s2;
static cudaEvent_t g_e1, g_e2;
static struct StreamInit {
    StreamInit() {
        cudaStreamCreateWithFlags(&g_s2, cudaStreamNonBlocking);
        cudaEventCreateWithFlags(&g_e1, cudaEventDisableTiming);
        cudaEventCreateWithFlags(&g_e2, cudaEventDisableTiming);
    }
} g_stream_init;

extern "C" void kernel_launch(void* const* d_in, const int* in_sizes, int n_in,
                              void* d_out, int out_size) {
    const float* h       = (const float*)d_in[0];  // (B,L,768)
    const float* age     = (const float*)d_in[1];  // (B,L)
    const float* tage    = (const float*)d_in[2];  // (B,L)
    const int*   targets = (const int*)d_in[4];    // (B,L) int32
    const float* W1      = (const float*)d_in[5];  // (768,256)
    const float* W2      = (const float*)d_in[6];  // (32,1280)
    float* out = (float*)d_out;

    // Fork: seed -> tte_write on stream 2; prep -> gemm1t -> gemm2m on 0.
    cudaEventRecord(g_e1, 0);
    cudaStreamWaitEvent(g_s2, g_e1, 0);
    k_seed<<<dim3(5, B_), 256, 0, g_s2>>>(targets);
    k_tte_write<<<dim3(64, B_), 320, 0, g_s2>>>(targets, age, tage, out);
    cudaEventRecord(g_e2, g_s2);

    k_prep<<<192, 256>>>(W1);
    k_gemm1t<<<dim3(4, 64), 128>>>(h);
    k_gemm2m<<<dim3(20, 256), 256>>>(W2, out);
    cudaStreamWaitEvent(0, g_e2, 0);
}